// round 11
// baseline (speedup 1.0000x reference)
#include <cuda_runtime.h>
#include <cuda_bf16.h>
#include <math.h>

// Problem dims
#define BB 32
#define SS 512
#define HH 128
#define NHEADS 4
#define DD 32
#define FFD 512
#define NN 16
#define SNN 64
#define ROWS (BB*SS)          // 16384

// ---------------- static device scratch ----------------
__device__ float g_xn  [ROWS*HH];
__device__ float g_qkv [ROWS*384];
__device__ float g_attn[ROWS*HH];
__device__ float g_x1  [ROWS*HH];
__device__ float g_h   [ROWS*HH];
__device__ float g_ffh [ROWS*FFD];
__device__ float g_x2  [ROWS*HH];
__device__ float g_A   [ROWS*HH];
__device__ float g_xnei[BB*NN*HH];
__device__ float g_Bn  [BB*NN*HH];
__device__ float g_Wd  [HH*HH];
__device__ float g_Wnc [HH*HH];
__device__ float g_Wqkv[HH*384];
__device__ float g_bqkv[384];

// ---------------- tf32 / mma / cp.async helpers ----------------------------
__device__ __forceinline__ unsigned f2tf(float f) {
    unsigned r;
    asm("cvt.rna.tf32.f32 %0, %1;" : "=r"(r) : "f"(f));
    return r;
}
__device__ __forceinline__ float f2tf_f(float f) { return __uint_as_float(f2tf(f)); }

__device__ __forceinline__ void mma_tf32(float* c, const unsigned* a, const unsigned* b) {
    asm volatile(
        "mma.sync.aligned.m16n8k8.row.col.f32.tf32.tf32.f32 "
        "{%0,%1,%2,%3}, {%4,%5,%6,%7}, {%8,%9}, {%0,%1,%2,%3};"
        : "+f"(c[0]), "+f"(c[1]), "+f"(c[2]), "+f"(c[3])
        : "r"(a[0]), "r"(a[1]), "r"(a[2]), "r"(a[3]), "r"(b[0]), "r"(b[1]));
}

__device__ __forceinline__ void cp16(void* smem, const void* gmem) {
    unsigned s = (unsigned)__cvta_generic_to_shared(smem);
    asm volatile("cp.async.cg.shared.global [%0], [%1], 16;\n" :: "r"(s), "l"(gmem));
}
#define CP_COMMIT() asm volatile("cp.async.commit_group;\n" ::: "memory")
#define CP_WAIT(n)  asm volatile("cp.async.wait_group %0;\n" :: "n"(n) : "memory")

// pair-permutation within groups of 8 k-indices: k and k+4 become adjacent
__device__ __host__ __forceinline__ int kpos(int k) {
    return (k & ~7) | ((k & 3) << 1) | ((k >> 2) & 1);
}

// ---------------- fast exp: FMA-pipe polynomial (no MUFU) ----------------
__device__ __forceinline__ float fast_exp(float x) {
    float z = x * 1.4426950408889634f;
    z = fminf(fmaxf(z, -126.0f), 126.0f);
    float t = z + 12582912.0f;
    int n = __float_as_int(t) - 0x4B400000;
    float f = z - (t - 12582912.0f);
    float p = 0.0013333558f;
    p = fmaf(p, f, 0.0096181291f);
    p = fmaf(p, f, 0.0555041087f);
    p = fmaf(p, f, 0.2402265070f);
    p = fmaf(p, f, 0.6931471806f);
    p = fmaf(p, f, 1.0f);
    return __int_as_float(__float_as_int(p) + (n << 23));
}

__device__ __forceinline__ float gelu_fast(float x) {
    float u = 0.7978845608028654f * (x + 0.044715f * x * x * x);
    float t = fast_exp(-2.0f * u);
    return __fdividef(x, 1.0f + t);
}

// ---------------- prep ------------------------------------------------------
__global__ void prep_kernel(const float* __restrict__ au_w1,
                            const float* __restrict__ wq, const float* __restrict__ wk,
                            const float* __restrict__ wv,
                            const float* __restrict__ bq, const float* __restrict__ bk,
                            const float* __restrict__ bv,
                            float* __restrict__ Wd, float* __restrict__ Wnc,
                            float* __restrict__ Wqkv, float* __restrict__ bqkv) {
    int idx = blockIdx.x * blockDim.x + threadIdx.x;
    if (idx < HH * HH) {
        int h = idx >> 7, j = idx & 127;
        float w1 = au_w1[h * HH + j];
        float w3 = au_w1[(256 + h) * HH + j];
        float w4 = au_w1[(384 + h) * HH + j];
        Wd[idx]  = w1 - w3;
        Wnc[idx] = w3 + w4;
    }
    if (idx < HH * 384) {
        int h = idx / 384, c = idx % 384;
        float v = (c < 128) ? wq[h * 128 + c]
                 : (c < 256) ? wk[h * 128 + (c - 128)]
                             : wv[h * 128 + (c - 256)];
        Wqkv[idx] = v;
    }
    if (idx < 384) {
        bqkv[idx] = (idx < 128) ? bq[idx] : (idx < 256) ? bk[idx - 128] : bv[idx - 256];
    }
}

// ---------------- layernorm ------------------------------------------------
__global__ void ln_kernel(const float* __restrict__ x, const float* __restrict__ g,
                          const float* __restrict__ b, float* __restrict__ y) {
    int row = blockIdx.x;
    int t = threadIdx.x;
    float v = x[(size_t)row * HH + t];
    float s = v, s2 = v * v;
    #pragma unroll
    for (int o = 16; o > 0; o >>= 1) {
        s  += __shfl_xor_sync(0xffffffffu, s, o);
        s2 += __shfl_xor_sync(0xffffffffu, s2, o);
    }
    __shared__ float ws[8];
    if ((t & 31) == 0) { ws[t >> 5] = s; ws[4 + (t >> 5)] = s2; }
    __syncthreads();
    s  = ws[0] + ws[1] + ws[2] + ws[3];
    s2 = ws[4] + ws[5] + ws[6] + ws[7];
    float mean = s * (1.0f / HH);
    float var = s2 * (1.0f / HH) - mean * mean;
    float rs = rsqrtf(var + 1e-6f);
    y[(size_t)row * HH + t] = (v - mean) * rs * g[t] + b[t];
}

// ---------------- TF32 tensor-core GEMM: cp.async double-buffered ----------
#define TBM 128
#define TBN 128
#define TBK 16
__device__ __forceinline__ void gemm_issue_tile(
    const float* __restrict__ A, const float* __restrict__ W,
    float (*As)[20], float (*Ws)[132],
    int bm, int bn, int K, int N, int k0, int tid) {
    #pragma unroll
    for (int l = 0; l < 2; l++) {
        int ch = l * 256 + tid;
        int ar = ch >> 2, ac = ch & 3;          // 128 rows x 4 chunks
        cp16(&As[ar][ac * 4], &A[(size_t)(bm + ar) * K + k0 + ac * 4]);
        int wr = ch >> 5, wc = ch & 31;         // 16 rows x 32 chunks
        cp16(&Ws[wr][wc * 4], &W[(size_t)(k0 + wr) * N + bn + wc * 4]);
    }
}

__global__ __launch_bounds__(256) void sgemm_tc(
    const float* __restrict__ A, const float* __restrict__ W,
    const float* __restrict__ bias, const float* __restrict__ res,
    float* __restrict__ C, int M, int K, int N, int act) {
    __shared__ float As[2][TBM][20];
    __shared__ float Ws[2][TBK][132];
    int bm = blockIdx.y * TBM, bn = blockIdx.x * TBN;
    int tid = threadIdx.x;
    int wid = tid >> 5, lane = tid & 31;
    int gid = lane >> 2, tig = lane & 3;
    int wm = (wid >> 2) * 64, wn = (wid & 3) * 32;
    gemm_issue_tile(A, W, As[0], Ws[0], bm, bn, K, N, 0, tid);
    CP_COMMIT();
    float c[4][4][4] = {};
    int nk = K / TBK;
    for (int kt = 0; kt < nk; kt++) {
        int cur = kt & 1;
        if (kt + 1 < nk) {
            gemm_issue_tile(A, W, As[cur ^ 1], Ws[cur ^ 1], bm, bn, K, N, (kt + 1) * TBK, tid);
            CP_COMMIT();
            CP_WAIT(1);
        } else {
            CP_WAIT(0);
        }
        __syncthreads();
        #pragma unroll
        for (int ks = 0; ks < 2; ks++) {
            int k0 = ks * 8;
            unsigned a[4][4], b[4][2];
            #pragma unroll
            for (int mt = 0; mt < 4; mt++) {
                a[mt][0] = __float_as_uint(As[cur][wm + mt * 16 + gid    ][k0 + tig]);
                a[mt][1] = __float_as_uint(As[cur][wm + mt * 16 + gid + 8][k0 + tig]);
                a[mt][2] = __float_as_uint(As[cur][wm + mt * 16 + gid    ][k0 + tig + 4]);
                a[mt][3] = __float_as_uint(As[cur][wm + mt * 16 + gid + 8][k0 + tig + 4]);
            }
            #pragma unroll
            for (int nt = 0; nt < 4; nt++) {
                b[nt][0] = __float_as_uint(Ws[cur][k0 + tig    ][wn + nt * 8 + gid]);
                b[nt][1] = __float_as_uint(Ws[cur][k0 + tig + 4][wn + nt * 8 + gid]);
            }
            #pragma unroll
            for (int mt = 0; mt < 4; mt++)
                #pragma unroll
                for (int nt = 0; nt < 4; nt++)
                    mma_tf32(c[mt][nt], a[mt], b[nt]);
        }
        __syncthreads();
    }
    // epilogue
    #pragma unroll
    for (int mt = 0; mt < 4; mt++) {
        #pragma unroll
        for (int nt = 0; nt < 4; nt++) {
            int col = bn + wn + nt * 8 + tig * 2;
            float b0 = bias ? bias[col] : 0.0f;
            float b1 = bias ? bias[col + 1] : 0.0f;
            #pragma unroll
            for (int hh = 0; hh < 2; hh++) {
                int row = bm + wm + mt * 16 + gid + hh * 8;
                float v0 = c[mt][nt][hh * 2 + 0] + b0;
                float v1 = c[mt][nt][hh * 2 + 1] + b1;
                if (act == 1) { v0 = gelu_fast(v0); v1 = gelu_fast(v1); }
                if (res) {
                    const float2 rv = *(const float2*)&res[(size_t)row * N + col];
                    v0 += rv.x; v1 += rv.y;
                }
                float2 ov; ov.x = v0; ov.y = v1;
                *(float2*)&C[(size_t)row * N + col] = ov;
            }
        }
    }
}

// ---------------- flash attention: cp.async pipeline, Q in regs ------------
__global__ __launch_bounds__(128, 5) void attn_kernel(const float* __restrict__ qkv,
                                                      const int* __restrict__ mask,
                                                      float* __restrict__ o) {
    __shared__ float Ks[2][64][36];
    __shared__ float Vs[2][64][36];
    int blk = blockIdx.x;
    int qt = blk & 7, h = (blk >> 3) & 3, b = blk >> 5;
    int q0 = qt * 64;
    int tid = threadIdx.x;
    int w = tid >> 5, lane = tid & 31;
    int gid = lane >> 2, tig = lane & 3;
    const float* qbase = qkv + (size_t)(b * SS + q0) * 384 + h * 32;
    const float* kbase = qkv + (size_t)b * SS * 384 + 128 + h * 32;
    const float* vbase = qkv + (size_t)b * SS * 384 + 256 + h * 32;
    const float scale = 0.17677669529663687f;
    // stage Q through Ks[0], then hold fragments in registers
    #pragma unroll
    for (int k = 0; k < 4; k++) {
        int idx = tid + k * 128;
        int r = idx >> 3, c4 = idx & 7;
        float4 v = *(const float4*)&qbase[(size_t)r * 384 + c4 * 4];
        v.x *= scale; v.y *= scale; v.z *= scale; v.w *= scale;
        *(float4*)&Ks[0][r][c4 * 4] = v;
    }
    __syncthreads();
    unsigned qa[4][4];
    #pragma unroll
    for (int ks = 0; ks < 4; ks++) {
        int k0 = ks * 8;
        qa[ks][0] = __float_as_uint(Ks[0][w * 16 + gid    ][k0 + tig]);
        qa[ks][1] = __float_as_uint(Ks[0][w * 16 + gid + 8][k0 + tig]);
        qa[ks][2] = __float_as_uint(Ks[0][w * 16 + gid    ][k0 + tig + 4]);
        qa[ks][3] = __float_as_uint(Ks[0][w * 16 + gid + 8][k0 + tig + 4]);
    }
    __syncthreads();
    // issue K/V tile 0 (overwrites the Q staging area)
    #pragma unroll
    for (int k = 0; k < 4; k++) {
        int idx = tid + k * 128;
        int r = idx >> 3, c4 = idx & 7;
        cp16(&Ks[0][r][c4 * 4], &kbase[(size_t)r * 384 + c4 * 4]);
        cp16(&Vs[0][r][c4 * 4], &vbase[(size_t)r * 384 + c4 * 4]);
    }
    CP_COMMIT();
    float o_acc[4][4] = {};
    float m0 = -1e30f, l0 = 0.0f, m1 = -1e30f, l1 = 0.0f;
    const int* mbase = mask + (size_t)b * SS * SS + (size_t)q0 * SS;
    int src0 = (lane & ~3) + (tig >> 1);
    int src2 = src0 + 2;
    bool oddc = (tig & 1) != 0;
    for (int kt = 0; kt < 8; kt++) {
        int cur = kt & 1;
        if (kt + 1 < 8) {
            int cn = (kt + 1) * 64;
            #pragma unroll
            for (int k = 0; k < 4; k++) {
                int idx = tid + k * 128;
                int r = idx >> 3, c4 = idx & 7;
                cp16(&Ks[cur ^ 1][r][c4 * 4], &kbase[(size_t)(cn + r) * 384 + c4 * 4]);
                cp16(&Vs[cur ^ 1][r][c4 * 4], &vbase[(size_t)(cn + r) * 384 + c4 * 4]);
            }
            CP_COMMIT();
            CP_WAIT(1);
        } else {
            CP_WAIT(0);
        }
        __syncthreads();
        int c0k = kt * 64;
        // S = Q @ K^T : per-warp 16x64; cs doubles as P storage (in-place)
        float cs[8][4] = {};
        #pragma unroll
        for (int ks = 0; ks < 4; ks++) {
            int k0 = ks * 8;
            #pragma unroll
            for (int nt = 0; nt < 8; nt++) {
                unsigned bb[2];
                bb[0] = __float_as_uint(Ks[cur][nt * 8 + gid][k0 + tig]);
                bb[1] = __float_as_uint(Ks[cur][nt * 8 + gid][k0 + tig + 4]);
                mma_tf32(cs[nt], qa[ks], bb);
            }
        }
        // mask (int2), in place
        const int2* mr0 = (const int2*)(mbase + (size_t)(w * 16 + gid) * SS + c0k);
        const int2* mr1 = (const int2*)(mbase + (size_t)(w * 16 + gid + 8) * SS + c0k);
        #pragma unroll
        for (int nt = 0; nt < 8; nt++) {
            int2 m0v = mr0[nt * 4 + tig];
            int2 m1v = mr1[nt * 4 + tig];
            if (m0v.x == 0) cs[nt][0] = -1e9f;
            if (m0v.y == 0) cs[nt][1] = -1e9f;
            if (m1v.x == 0) cs[nt][2] = -1e9f;
            if (m1v.y == 0) cs[nt][3] = -1e9f;
        }
        // online softmax, in place on cs
        float t0 = cs[0][0], t1 = cs[0][2];
        #pragma unroll
        for (int nt = 0; nt < 8; nt++) {
            t0 = fmaxf(t0, fmaxf(cs[nt][0], cs[nt][1]));
            t1 = fmaxf(t1, fmaxf(cs[nt][2], cs[nt][3]));
        }
        t0 = fmaxf(t0, __shfl_xor_sync(0xffffffffu, t0, 1));
        t0 = fmaxf(t0, __shfl_xor_sync(0xffffffffu, t0, 2));
        t1 = fmaxf(t1, __shfl_xor_sync(0xffffffffu, t1, 1));
        t1 = fmaxf(t1, __shfl_xor_sync(0xffffffffu, t1, 2));
        float mn0 = fmaxf(m0, t0), mn1 = fmaxf(m1, t1);
        float corr0 = fast_exp(m0 - mn0), corr1 = fast_exp(m1 - mn1);
        float ps0 = 0.0f, ps1 = 0.0f;
        #pragma unroll
        for (int nt = 0; nt < 8; nt++) {
            cs[nt][0] = fast_exp(cs[nt][0] - mn0);
            cs[nt][1] = fast_exp(cs[nt][1] - mn0);
            cs[nt][2] = fast_exp(cs[nt][2] - mn1);
            cs[nt][3] = fast_exp(cs[nt][3] - mn1);
            ps0 += cs[nt][0] + cs[nt][1];
            ps1 += cs[nt][2] + cs[nt][3];
        }
        ps0 += __shfl_xor_sync(0xffffffffu, ps0, 1);
        ps0 += __shfl_xor_sync(0xffffffffu, ps0, 2);
        ps1 += __shfl_xor_sync(0xffffffffu, ps1, 1);
        ps1 += __shfl_xor_sync(0xffffffffu, ps1, 2);
        l0 = l0 * corr0 + ps0; m0 = mn0;
        l1 = l1 * corr1 + ps1; m1 = mn1;
        #pragma unroll
        for (int nt = 0; nt < 4; nt++) {
            o_acc[nt][0] *= corr0; o_acc[nt][1] *= corr0;
            o_acc[nt][2] *= corr1; o_acc[nt][3] *= corr1;
        }
        // O += P @ V : P fragments via intra-quad shuffles on cs, raw bits
        #pragma unroll
        for (int ks = 0; ks < 8; ks++) {
            float lo0 = __shfl_sync(0xffffffffu, cs[ks][0], src0);
            float hi0 = __shfl_sync(0xffffffffu, cs[ks][1], src0);
            float lo1 = __shfl_sync(0xffffffffu, cs[ks][2], src0);
            float hi1 = __shfl_sync(0xffffffffu, cs[ks][3], src0);
            float lo2 = __shfl_sync(0xffffffffu, cs[ks][0], src2);
            float hi2 = __shfl_sync(0xffffffffu, cs[ks][1], src2);
            float lo3 = __shfl_sync(0xffffffffu, cs[ks][2], src2);
            float hi3 = __shfl_sync(0xffffffffu, cs[ks][3], src2);
            unsigned a[4];
            a[0] = __float_as_uint(oddc ? hi0 : lo0);
            a[1] = __float_as_uint(oddc ? hi1 : lo1);
            a[2] = __float_as_uint(oddc ? hi2 : lo2);
            a[3] = __float_as_uint(oddc ? hi3 : lo3);
            int k0 = ks * 8;
            #pragma unroll
            for (int nt = 0; nt < 4; nt++) {
                unsigned bb[2];
                bb[0] = __float_as_uint(Vs[cur][k0 + tig    ][nt * 8 + gid]);
                bb[1] = __float_as_uint(Vs[cur][k0 + tig + 4][nt * 8 + gid]);
                mma_tf32(o_acc[nt], a, bb);
            }
        }
        __syncthreads();
    }
    // epilogue
    float inv0 = __fdividef(1.0f, l0);
    float inv1 = __fdividef(1.0f, l1);
    #pragma unroll
    for (int nt = 0; nt < 4; nt++) {
        int col = h * 32 + nt * 8 + tig * 2;
        size_t row0 = (size_t)(b * SS + q0 + w * 16 + gid);
        float2 v0; v0.x = o_acc[nt][0] * inv0; v0.y = o_acc[nt][1] * inv0;
        *(float2*)&o[row0 * HH + col] = v0;
        float2 v1; v1.x = o_acc[nt][2] * inv1; v1.y = o_acc[nt][3] * inv1;
        *(float2*)&o[(row0 + 8) * HH + col] = v1;
    }
}

// ---------------- neighbor proj helper -------------------------------------
__device__ __forceinline__ void proj64(const float* ln, const float* __restrict__ W,
                                       const float* __restrict__ bias, float* out, int tid) {
    int c2 = (tid & 63) * 2;
    int q4 = tid >> 6;
    int r0 = q4 * 16;
    float acc0[16], acc1[16];
    float bv0 = bias[c2], bv1 = bias[c2 + 1];
    #pragma unroll
    for (int i = 0; i < 16; i++) { acc0[i] = bv0; acc1[i] = bv1; }
    #pragma unroll 4
    for (int hh = 0; hh < HH; hh++) {
        float2 w = *(const float2*)&W[hh * HH + c2];
        #pragma unroll
        for (int i = 0; i < 16; i++) {
            float a = ln[(r0 + i) * 129 + hh];
            acc0[i] += a * w.x;
            acc1[i] += a * w.y;
        }
    }
    #pragma unroll
    for (int i = 0; i < 16; i++) {
        out[(r0 + i) * 129 + c2] = acc0[i];
        out[(r0 + i) * 129 + c2 + 1] = acc1[i];
    }
}

// ---------------- neighbor attention (last-token only) + fused Bn ----------
__global__ void neigh_kernel(const float* __restrict__ neighs, const int* __restrict__ nmask,
                             const float* __restrict__ wq, const float* __restrict__ bq,
                             const float* __restrict__ wk, const float* __restrict__ bk,
                             const float* __restrict__ wv, const float* __restrict__ bv,
                             const float* __restrict__ wo, const float* __restrict__ bo,
                             const float* __restrict__ g1, const float* __restrict__ b1,
                             const float* __restrict__ Wnc,
                             float* __restrict__ xnei, float* __restrict__ Bn) {
    extern __shared__ float sh[];
    float* ln  = sh;
    float* kv  = ln + 64 * 129;
    float* qv  = kv + 64 * 129;
    float* osh = qv + 128;
    float* sc  = osh + 128;
    int tid = threadIdx.x;
    int nb = blockIdx.x;
    int n = nb / BB, b = nb % BB;
    const float* base = neighs + (size_t)nb * SNN * HH;
    for (int idx = tid; idx < SNN * HH; idx += 256) {
        int r = idx >> 7, c = idx & 127;
        ln[r * 129 + c] = base[idx];
    }
    __syncthreads();
    {
        int warp = tid >> 5, lane = tid & 31;
        for (int r = warp; r < SNN; r += 8) {
            float s = 0.0f, s2 = 0.0f;
            #pragma unroll
            for (int c = lane; c < HH; c += 32) {
                float v = ln[r * 129 + c];
                s += v; s2 += v * v;
            }
            #pragma unroll
            for (int o = 16; o > 0; o >>= 1) {
                s  += __shfl_xor_sync(0xffffffffu, s, o);
                s2 += __shfl_xor_sync(0xffffffffu, s2, o);
            }
            float mean = s * (1.0f / HH);
            float var = s2 * (1.0f / HH) - mean * mean;
            float rs = rsqrtf(var + 1e-6f);
            #pragma unroll
            for (int c = lane; c < HH; c += 32) {
                float v = ln[r * 129 + c];
                ln[r * 129 + c] = (v - mean) * rs * g1[c] + b1[c];
            }
        }
    }
    __syncthreads();
    proj64(ln, wk, bk, kv, tid);
    if (tid < HH) {
        float a = bq[tid];
        #pragma unroll 4
        for (int hh = 0; hh < HH; hh++) a += ln[63 * 129 + hh] * wq[hh * HH + tid];
        qv[tid] = a;
    }
    __syncthreads();
    {
        int head = tid >> 6, j = tid & 63;
        float s = 0.0f;
        #pragma unroll
        for (int d = 0; d < DD; d++) s += qv[head * DD + d] * kv[j * 129 + head * DD + d];
        s *= 0.17677669529663687f;
        int mval = nmask[((size_t)nb * SNN + (SNN - 1)) * SNN + j];
        if (mval == 0) s = -1e9f;
        sc[head * 64 + j] = s;
    }
    __syncthreads();
    if (tid < 4) {
        float m = -1e30f;
        for (int j = 0; j < 64; j++) m = fmaxf(m, sc[tid * 64 + j]);
        float l = 0.0f;
        for (int j = 0; j < 64; j++) {
            float p = fast_exp(sc[tid * 64 + j] - m);
            sc[tid * 64 + j] = p; l += p;
        }
        float inv = 1.0f / l;
        for (int j = 0; j < 64; j++) sc[tid * 64 + j] *= inv;
    }
    __syncthreads();
    proj64(ln, wv, bv, kv, tid);
    __syncthreads();
    if (tid < HH) {
        int head = tid >> 5;
        float o = 0.0f;
        #pragma unroll 4
        for (int j = 0; j < 64; j++) o += sc[head * 64 + j] * kv[j * 129 + tid];
        osh[tid] = o;
    }
    __syncthreads();
    if (tid < HH) {
        float r = bo[tid] + base[(SNN - 1) * HH + tid];
        #pragma unroll 4
        for (int hh = 0; hh < HH; hh++) r += osh[hh] * wo[hh * HH + tid];
        xnei[((size_t)b * NN + n) * HH + tid] = r;
        qv[tid] = r;                            // stash for Bn pass
    }
    __syncthreads();
    // fused Bn = xnei_row @ Wnc : 256 threads, split K in halves
    {
        int col = tid & 127;
        int kh = (tid >> 7) * 64;
        float acc = 0.0f;
        #pragma unroll 4
        for (int k = 0; k < 64; k++)
            acc += qv[kh + k] * Wnc[(size_t)(kh + k) * HH + col];
        sc[tid] = acc;
    }
    __syncthreads();
    if (tid < HH)
        Bn[((size_t)b * NN + n) * HH + tid] = sc[tid] + sc[tid + 128];
}

// ---------------- attention-pooling kernel (tf32 mma, paired LDS.64) -------
// kpos-paired smem layouts: every fragment pair (k, k+4) is one LDS.64.
__global__ __launch_bounds__(256) void au_kernel(
        const float* __restrict__ x2, const float* __restrict__ Ag,
        const float* __restrict__ Bng, const float* __restrict__ xnei,
        const float* __restrict__ au_w1, const float* __restrict__ au_w2,
        const float* __restrict__ au_b2, float* __restrict__ out) {
    extern __shared__ float sh[];
    float* x2sP   = sh;                  // 64*132  (row, kpos) tf32
    float* W2sT   = x2sP + 64 * 132;     // 128*132 (col, kpos) tf32
    float* xnsP   = W2sT + 128 * 132;    // 16*132  (n, kpos) fp32
    float* logits = xnsP + 16 * 132;     // 64*16
    int tid = threadIdx.x;
    int b = blockIdx.y;
    int s0 = blockIdx.x * 64;
    int w = tid >> 5, lane = tid & 31;
    int gid = lane >> 2, tig = lane & 3;
    int wn = w * 16;
    for (int idx = tid; idx < HH * HH; idx += 256) {
        int k = idx >> 7, nn = idx & 127;
        W2sT[nn * 132 + kpos(k)] = f2tf_f(au_w1[HH * HH + idx]);
    }
    for (int idx = tid; idx < 64 * HH; idx += 256) {
        int r = idx >> 7, cc = idx & 127;
        x2sP[r * 132 + kpos(cc)] = f2tf_f(x2[((size_t)b * SS + s0 + r) * HH + cc]);
    }
    for (int idx = tid; idx < NN * HH; idx += 256) {
        int n = idx >> 7, k = idx & 127;
        xnsP[n * 132 + kpos(k)] = xnei[(size_t)b * NN * HH + idx];
    }
    for (int idx = tid; idx < 64 * 16; idx += 256) logits[idx] = 0.0f;
    int colv[4];
    float w2r[4];
    #pragma unroll
    for (int q = 0; q < 4; q++) {
        colv[q] = wn + (q >> 1) * 8 + tig * 2 + (q & 1);
        w2r[q] = au_w2[colv[q]];
    }
    float Areg[8][4];
    #pragma unroll
    for (int mt = 0; mt < 4; mt++)
        #pragma unroll
        for (int hh = 0; hh < 2; hh++) {
            int r = mt * 16 + gid + hh * 8;
            #pragma unroll
            for (int q = 0; q < 4; q++)
                Areg[mt * 2 + hh][q] = Ag[((size_t)b * SS + s0 + r) * HH + colv[q]];
        }
    __syncthreads();
    for (int n = 0; n < NN; n++) {
        float c[4][2][4] = {};
        #pragma unroll
        for (int ks = 0; ks < 16; ks++) {
            int k0 = ks * 8;
            // one LDS.64 gives the (k0+tig, k0+tig+4) pair
            float2 xn2 = *(float2*)&xnsP[n * 132 + k0 + tig * 2];
            unsigned bfr[2][2];
            #pragma unroll
            for (int nt = 0; nt < 2; nt++) {
                float2 wv2 = *(float2*)&W2sT[(wn + nt * 8 + gid) * 132 + k0 + tig * 2];
                bfr[nt][0] = __float_as_uint(wv2.x * xn2.x);   // raw bits -> tf32 trunc
                bfr[nt][1] = __float_as_uint(wv2.y * xn2.y);
            }
            #pragma unroll
            for (int mt = 0; mt < 4; mt++) {
                float2 alo = *(float2*)&x2sP[(mt * 16 + gid) * 132 + k0 + tig * 2];
                float2 ahi = *(float2*)&x2sP[(mt * 16 + gid + 8) * 132 + k0 + tig * 2];
                unsigned a[4];
                a[0] = __float_as_uint(alo.x);
                a[1] = __float_as_uint(ahi.x);
                a[2] = __float_as_uint(alo.y);
                a[3] = __float_as_uint(ahi.y);
                mma_tf32(c[mt][0], a, bfr[0]);
                mma_tf32(c[mt][1], a, bfr[1]);
            }
        }
        float BnR[4];
        #pragma unroll
        for (int q = 0; q < 4; q++)
            BnR[q] = Bng[((size_t)b * NN + n) * HH + colv[q]];
        #pragma unroll
        for (int mt = 0; mt < 4; mt++) {
            float part0 = 0.0f, part1 = 0.0f;
            #pragma unroll
            for (int nt = 0; nt < 2; nt++)
                #pragma unroll
                for (int cc = 0; cc < 2; cc++) {
                    int q = nt * 2 + cc;
                    float v0 = c[mt][nt][cc]     + Areg[mt * 2][q]     + BnR[q];
                    float v1 = c[mt][nt][2 + cc] + Areg[mt * 2 + 1][q] + BnR[q];
                    part0 += fmaxf(v0, 0.0f) * w2r[q];
                    part1 += fmaxf(v1, 0.0f) * w2r[q];
                }
            part0 += __shfl_xor_sync(0xffffffffu, part0, 1);
            part0 += __shfl_xor_sync(0xffffffffu, part0, 2);
            part1 += __shfl_xor_sync(0xffffffffu, part1, 1);
            part1 += __shfl_xor_sync(0xffffffffu, part1, 2);
            if (tig == 0) {
                atomicAdd(&logits[(mt * 16 + gid) * 16 + n], part0);
                atomicAdd(&logits[(mt * 16 + gid + 8) * 16 + n], part1);
            }
        }
    }
    __syncthreads();
    if (tid < 64) {
        float m = -1e30f;
        #pragma unroll
        for (int n = 0; n < NN; n++) m = fmaxf(m, logits[tid * 16 + n]);
        float l = 0.0f;
        #pragma unroll
        for (int n = 0; n < NN; n++) {
            float p = fast_exp(logits[tid * 16 + n] - m);
            logits[tid * 16 + n] = p; l += p;
        }
        float inv = __fdividef(1.0f, l);
        #pragma unroll
        for (int n = 0; n < NN; n++) logits[tid * 16 + n] *= inv;
    }
    __syncthreads();
    for (int idx = tid; idx < 64 * HH; idx += 256) {
        int r = idx >> 7, cc = idx & 127;
        float o = x2[((size_t)b * SS + s0 + r) * HH + cc];
        int pc = kpos(cc);
        #pragma unroll
        for (int n = 0; n < NN; n++) o += logits[r * 16 + n] * xnsP[n * 132 + pc];
        out[((size_t)b * SS + s0 + r) * HH + cc] = o;
    }
}

// ---------------- launch ----------------
extern "C" void kernel_launch(void* const* d_in, const int* in_sizes, int n_in,
                              void* d_out, int out_size) {
    const float* x      = (const float*)d_in[0];
    const int*   mask   = (const int*)  d_in[1];
    const float* neighs = (const float*)d_in[2];
    const int*   nmask  = (const int*)  d_in[3];
    const float* wq = (const float*)d_in[4];  const float* bq = (const float*)d_in[5];
    const float* wk = (const float*)d_in[6];  const float* bk = (const float*)d_in[7];
    const float* wv = (const float*)d_in[8];  const float* bv = (const float*)d_in[9];
    const float* wo = (const float*)d_in[10]; const float* bo = (const float*)d_in[11];
    const float* ln1_g = (const float*)d_in[12]; const float* ln1_b = (const float*)d_in[13];
    const float* ln2_g = (const float*)d_in[14]; const float* ln2_b = (const float*)d_in[15];
    const float* ff_w1 = (const float*)d_in[16]; const float* ff_b1 = (const float*)d_in[17];
    const float* ff_w2 = (const float*)d_in[18]; const float* ff_b2 = (const float*)d_in[19];
    const float* au_w1 = (const float*)d_in[20]; const float* au_b1 = (const float*)d_in[21];
    const float* au_w2 = (const float*)d_in[22]; const float* au_b2 = (const float*)d_in[23];
    float* out = (float*)d_out;

    float *p_xn, *p_qkv, *p_attn, *p_x1, *p_h, *p_ffh, *p_x2, *p_A,
          *p_xnei, *p_Bn, *p_Wd, *p_Wnc, *p_Wqkv, *p_bqkv;
    cudaGetSymbolAddress((void**)&p_xn, g_xn);
    cudaGetSymbolAddress((void**)&p_qkv, g_qkv);
    cudaGetSymbolAddress((void**)&p_attn, g_attn);
    cudaGetSymbolAddress((void**)&p_x1, g_x1);
    cudaGetSymbolAddress((void**)&p_h, g_h);
    cudaGetSymbolAddress((void**)&p_ffh, g_ffh);
    cudaGetSymbolAddress((void**)&p_x2, g_x2);
    cudaGetSymbolAddress((void**)&p_A, g_A);
    cudaGetSymbolAddress((void**)&p_xnei, g_xnei);
    cudaGetSymbolAddress((void**)&p_Bn, g_Bn);
    cudaGetSymbolAddress((void**)&p_Wd, g_Wd);
    cudaGetSymbolAddress((void**)&p_Wnc, g_Wnc);
    cudaGetSymbolAddress((void**)&p_Wqkv, g_Wqkv);
    cudaGetSymbolAddress((void**)&p_bqkv, g_bqkv);

    const int neigh_shmem = (64 * 129 * 2 + 128 + 128 + 256) * 4;            // ~68 KB
    const int au_shmem = (64 * 132 + 128 * 132 + 16 * 132 + 64 * 16) * 4;    // 113,920 B
    cudaFuncSetAttribute(neigh_kernel, cudaFuncAttributeMaxDynamicSharedMemorySize, neigh_shmem);
    cudaFuncSetAttribute(au_kernel, cudaFuncAttributeMaxDynamicSharedMemorySize, au_shmem);

    prep_kernel<<<192, 256>>>(au_w1, wq, wk, wv, bq, bk, bv, p_Wd, p_Wnc, p_Wqkv, p_bqkv);
    ln_kernel<<<ROWS, 128>>>(x, ln1_g, ln1_b, p_xn);
    {
        dim3 g(384 / TBN, ROWS / TBM);
        sgemm_tc<<<g, 256>>>(p_xn, p_Wqkv, p_bqkv, nullptr, p_qkv, ROWS, HH, 384, 0);
    }
    attn_kernel<<<BB * NHEADS * 8, 128>>>(p_qkv, mask, p_attn);
    {
        dim3 g(1, ROWS / TBM);
        sgemm_tc<<<g, 256>>>(p_attn, wo, bo, x, p_x1, ROWS, HH, HH, 0);
    }
    neigh_kernel<<<NN * BB, 256, neigh_shmem>>>(neighs, nmask, wq, bq, wk, bk, wv, bv,
                                                wo, bo, ln1_g, ln1_b, p_Wnc, p_xnei, p_Bn);
    ln_kernel<<<ROWS, 128>>>(p_x1, ln2_g, ln2_b, p_h);
    {
        dim3 g(FFD / TBN, ROWS / TBM);
        sgemm_tc<<<g, 256>>>(p_h, ff_w1, ff_b1, nullptr, p_ffh, ROWS, HH, FFD, 1);
    }
    {
        dim3 g(1, ROWS / TBM);
        sgemm_tc<<<g, 256>>>(p_ffh, ff_w2, ff_b2, p_x1, p_x2, ROWS, FFD, HH, 0);
    }
    {
        dim3 g(1, ROWS / TBM);
        sgemm_tc<<<g, 256>>>(p_x2, p_Wd, au_b1, nullptr, p_A, ROWS, HH, HH, 0);
    }
    {
        dim3 g(SS / 64, BB);
        au_kernel<<<g, 256, au_shmem>>>(p_x2, p_A, p_Bn, p_xnei, au_w1, au_w2, au_b2, out);
    }
}

// round 12
// speedup vs baseline: 1.2630x; 1.2630x over previous
#include <cuda_runtime.h>
#include <cuda_bf16.h>
#include <math.h>

// Problem dims
#define BB 32
#define SS 512
#define HH 128
#define NHEADS 4
#define DD 32
#define FFD 512
#define NN 16
#define SNN 64
#define ROWS (BB*SS)          // 16384

// ---------------- static device scratch ----------------
__device__ float g_xn  [ROWS*HH];
__device__ float g_qkv [ROWS*384];
__device__ float g_attn[ROWS*HH];
__device__ float g_x1  [ROWS*HH];
__device__ float g_h   [ROWS*HH];
__device__ float g_ffh [ROWS*FFD];
__device__ float g_x2  [ROWS*HH];
__device__ float g_A   [ROWS*HH];
__device__ float g_xnei[BB*NN*HH];
__device__ float g_Bn  [BB*NN*HH];
__device__ float g_Wd  [HH*HH];
__device__ float g_Wnc [HH*HH];
__device__ float g_Wqkv[HH*384];
__device__ float g_bqkv[384];

// ---------------- tf32 / mma / cp.async helpers ----------------------------
__device__ __forceinline__ unsigned f2tf(float f) {
    unsigned r;
    asm("cvt.rna.tf32.f32 %0, %1;" : "=r"(r) : "f"(f));
    return r;
}
__device__ __forceinline__ float f2tf_f(float f) { return __uint_as_float(f2tf(f)); }

__device__ __forceinline__ void mma_tf32(float* c, const unsigned* a, const unsigned* b) {
    asm volatile(
        "mma.sync.aligned.m16n8k8.row.col.f32.tf32.tf32.f32 "
        "{%0,%1,%2,%3}, {%4,%5,%6,%7}, {%8,%9}, {%0,%1,%2,%3};"
        : "+f"(c[0]), "+f"(c[1]), "+f"(c[2]), "+f"(c[3])
        : "r"(a[0]), "r"(a[1]), "r"(a[2]), "r"(a[3]), "r"(b[0]), "r"(b[1]));
}

__device__ __forceinline__ void cp16(void* smem, const void* gmem) {
    unsigned s = (unsigned)__cvta_generic_to_shared(smem);
    asm volatile("cp.async.cg.shared.global [%0], [%1], 16;\n" :: "r"(s), "l"(gmem));
}
#define CP_COMMIT() asm volatile("cp.async.commit_group;\n" ::: "memory")
#define CP_WAIT(n)  asm volatile("cp.async.wait_group %0;\n" :: "n"(n) : "memory")

// ---------------- fast exp: FMA-pipe polynomial (no MUFU) ----------------
__device__ __forceinline__ float fast_exp(float x) {
    float z = x * 1.4426950408889634f;
    z = fminf(fmaxf(z, -126.0f), 126.0f);
    float t = z + 12582912.0f;
    int n = __float_as_int(t) - 0x4B400000;
    float f = z - (t - 12582912.0f);
    float p = 0.0013333558f;
    p = fmaf(p, f, 0.0096181291f);
    p = fmaf(p, f, 0.0555041087f);
    p = fmaf(p, f, 0.2402265070f);
    p = fmaf(p, f, 0.6931471806f);
    p = fmaf(p, f, 1.0f);
    return __int_as_float(__float_as_int(p) + (n << 23));
}

__device__ __forceinline__ float gelu_fast(float x) {
    float u = 0.7978845608028654f * (x + 0.044715f * x * x * x);
    float t = fast_exp(-2.0f * u);
    return __fdividef(x, 1.0f + t);
}

// ---------------- prep ------------------------------------------------------
__global__ void prep_kernel(const float* __restrict__ au_w1,
                            const float* __restrict__ wq, const float* __restrict__ wk,
                            const float* __restrict__ wv,
                            const float* __restrict__ bq, const float* __restrict__ bk,
                            const float* __restrict__ bv,
                            float* __restrict__ Wd, float* __restrict__ Wnc,
                            float* __restrict__ Wqkv, float* __restrict__ bqkv) {
    int idx = blockIdx.x * blockDim.x + threadIdx.x;
    if (idx < HH * HH) {
        int h = idx >> 7, j = idx & 127;
        float w1 = au_w1[h * HH + j];
        float w3 = au_w1[(256 + h) * HH + j];
        float w4 = au_w1[(384 + h) * HH + j];
        Wd[idx]  = w1 - w3;
        Wnc[idx] = w3 + w4;
    }
    if (idx < HH * 384) {
        int h = idx / 384, c = idx % 384;
        float v = (c < 128) ? wq[h * 128 + c]
                 : (c < 256) ? wk[h * 128 + (c - 128)]
                             : wv[h * 128 + (c - 256)];
        Wqkv[idx] = v;
    }
    if (idx < 384) {
        bqkv[idx] = (idx < 128) ? bq[idx] : (idx < 256) ? bk[idx - 128] : bv[idx - 256];
    }
}

// ---------------- layernorm ------------------------------------------------
__global__ void ln_kernel(const float* __restrict__ x, const float* __restrict__ g,
                          const float* __restrict__ b, float* __restrict__ y) {
    int row = blockIdx.x;
    int t = threadIdx.x;
    float v = x[(size_t)row * HH + t];
    float s = v, s2 = v * v;
    #pragma unroll
    for (int o = 16; o > 0; o >>= 1) {
        s  += __shfl_xor_sync(0xffffffffu, s, o);
        s2 += __shfl_xor_sync(0xffffffffu, s2, o);
    }
    __shared__ float ws[8];
    if ((t & 31) == 0) { ws[t >> 5] = s; ws[4 + (t >> 5)] = s2; }
    __syncthreads();
    s  = ws[0] + ws[1] + ws[2] + ws[3];
    s2 = ws[4] + ws[5] + ws[6] + ws[7];
    float mean = s * (1.0f / HH);
    float var = s2 * (1.0f / HH) - mean * mean;
    float rs = rsqrtf(var + 1e-6f);
    y[(size_t)row * HH + t] = (v - mean) * rs * g[t] + b[t];
}

// ---------------- TF32 tensor-core GEMM: cp.async double-buffered ----------
#define TBM 128
#define TBN 128
#define TBK 16
__device__ __forceinline__ void gemm_issue_tile(
    const float* __restrict__ A, const float* __restrict__ W,
    float (*As)[20], float (*Ws)[132],
    int bm, int bn, int K, int N, int k0, int tid) {
    #pragma unroll
    for (int l = 0; l < 2; l++) {
        int ch = l * 256 + tid;
        int ar = ch >> 2, ac = ch & 3;          // 128 rows x 4 chunks
        cp16(&As[ar][ac * 4], &A[(size_t)(bm + ar) * K + k0 + ac * 4]);
        int wr = ch >> 5, wc = ch & 31;         // 16 rows x 32 chunks
        cp16(&Ws[wr][wc * 4], &W[(size_t)(k0 + wr) * N + bn + wc * 4]);
    }
}

__global__ __launch_bounds__(256) void sgemm_tc(
    const float* __restrict__ A, const float* __restrict__ W,
    const float* __restrict__ bias, const float* __restrict__ res,
    float* __restrict__ C, int M, int K, int N, int act) {
    __shared__ float As[2][TBM][20];
    __shared__ float Ws[2][TBK][132];
    int bm = blockIdx.y * TBM, bn = blockIdx.x * TBN;
    int tid = threadIdx.x;
    int wid = tid >> 5, lane = tid & 31;
    int gid = lane >> 2, tig = lane & 3;
    int wm = (wid >> 2) * 64, wn = (wid & 3) * 32;
    gemm_issue_tile(A, W, As[0], Ws[0], bm, bn, K, N, 0, tid);
    CP_COMMIT();
    float c[4][4][4] = {};
    int nk = K / TBK;
    for (int kt = 0; kt < nk; kt++) {
        int cur = kt & 1;
        if (kt + 1 < nk) {
            gemm_issue_tile(A, W, As[cur ^ 1], Ws[cur ^ 1], bm, bn, K, N, (kt + 1) * TBK, tid);
            CP_COMMIT();
            CP_WAIT(1);
        } else {
            CP_WAIT(0);
        }
        __syncthreads();
        #pragma unroll
        for (int ks = 0; ks < 2; ks++) {
            int k0 = ks * 8;
            unsigned a[4][4], b[4][2];
            #pragma unroll
            for (int mt = 0; mt < 4; mt++) {
                a[mt][0] = __float_as_uint(As[cur][wm + mt * 16 + gid    ][k0 + tig]);
                a[mt][1] = __float_as_uint(As[cur][wm + mt * 16 + gid + 8][k0 + tig]);
                a[mt][2] = __float_as_uint(As[cur][wm + mt * 16 + gid    ][k0 + tig + 4]);
                a[mt][3] = __float_as_uint(As[cur][wm + mt * 16 + gid + 8][k0 + tig + 4]);
            }
            #pragma unroll
            for (int nt = 0; nt < 4; nt++) {
                b[nt][0] = __float_as_uint(Ws[cur][k0 + tig    ][wn + nt * 8 + gid]);
                b[nt][1] = __float_as_uint(Ws[cur][k0 + tig + 4][wn + nt * 8 + gid]);
            }
            #pragma unroll
            for (int mt = 0; mt < 4; mt++)
                #pragma unroll
                for (int nt = 0; nt < 4; nt++)
                    mma_tf32(c[mt][nt], a[mt], b[nt]);
        }
        __syncthreads();
    }
    // epilogue
    #pragma unroll
    for (int mt = 0; mt < 4; mt++) {
        #pragma unroll
        for (int nt = 0; nt < 4; nt++) {
            int col = bn + wn + nt * 8 + tig * 2;
            float b0 = bias ? bias[col] : 0.0f;
            float b1 = bias ? bias[col + 1] : 0.0f;
            #pragma unroll
            for (int hh = 0; hh < 2; hh++) {
                int row = bm + wm + mt * 16 + gid + hh * 8;
                float v0 = c[mt][nt][hh * 2 + 0] + b0;
                float v1 = c[mt][nt][hh * 2 + 1] + b1;
                if (act == 1) { v0 = gelu_fast(v0); v1 = gelu_fast(v1); }
                if (res) {
                    const float2 rv = *(const float2*)&res[(size_t)row * N + col];
                    v0 += rv.x; v1 += rv.y;
                }
                float2 ov; ov.x = v0; ov.y = v1;
                *(float2*)&C[(size_t)row * N + col] = ov;
            }
        }
    }
}

// ---------------- flash attention: cp.async pipeline, Q in regs ------------
__global__ __launch_bounds__(128, 5) void attn_kernel(const float* __restrict__ qkv,
                                                      const int* __restrict__ mask,
                                                      float* __restrict__ o) {
    __shared__ float Ks[2][64][36];
    __shared__ float Vs[2][64][36];
    int blk = blockIdx.x;
    int qt = blk & 7, h = (blk >> 3) & 3, b = blk >> 5;
    int q0 = qt * 64;
    int tid = threadIdx.x;
    int w = tid >> 5, lane = tid & 31;
    int gid = lane >> 2, tig = lane & 3;
    const float* qbase = qkv + (size_t)(b * SS + q0) * 384 + h * 32;
    const float* kbase = qkv + (size_t)b * SS * 384 + 128 + h * 32;
    const float* vbase = qkv + (size_t)b * SS * 384 + 256 + h * 32;
    const float scale = 0.17677669529663687f;
    // stage Q through Ks[0], then hold fragments in registers
    #pragma unroll
    for (int k = 0; k < 4; k++) {
        int idx = tid + k * 128;
        int r = idx >> 3, c4 = idx & 7;
        float4 v = *(const float4*)&qbase[(size_t)r * 384 + c4 * 4];
        v.x *= scale; v.y *= scale; v.z *= scale; v.w *= scale;
        *(float4*)&Ks[0][r][c4 * 4] = v;
    }
    __syncthreads();
    unsigned qa[4][4];
    #pragma unroll
    for (int ks = 0; ks < 4; ks++) {
        int k0 = ks * 8;
        qa[ks][0] = __float_as_uint(Ks[0][w * 16 + gid    ][k0 + tig]);
        qa[ks][1] = __float_as_uint(Ks[0][w * 16 + gid + 8][k0 + tig]);
        qa[ks][2] = __float_as_uint(Ks[0][w * 16 + gid    ][k0 + tig + 4]);
        qa[ks][3] = __float_as_uint(Ks[0][w * 16 + gid + 8][k0 + tig + 4]);
    }
    __syncthreads();
    // issue K/V tile 0 (overwrites the Q staging area)
    #pragma unroll
    for (int k = 0; k < 4; k++) {
        int idx = tid + k * 128;
        int r = idx >> 3, c4 = idx & 7;
        cp16(&Ks[0][r][c4 * 4], &kbase[(size_t)r * 384 + c4 * 4]);
        cp16(&Vs[0][r][c4 * 4], &vbase[(size_t)r * 384 + c4 * 4]);
    }
    CP_COMMIT();
    float o_acc[4][4] = {};
    float m0 = -1e30f, l0 = 0.0f, m1 = -1e30f, l1 = 0.0f;
    const int* mbase = mask + (size_t)b * SS * SS + (size_t)q0 * SS;
    int src0 = (lane & ~3) + (tig >> 1);
    int src2 = src0 + 2;
    bool oddc = (tig & 1) != 0;
    for (int kt = 0; kt < 8; kt++) {
        int cur = kt & 1;
        if (kt + 1 < 8) {
            int cn = (kt + 1) * 64;
            #pragma unroll
            for (int k = 0; k < 4; k++) {
                int idx = tid + k * 128;
                int r = idx >> 3, c4 = idx & 7;
                cp16(&Ks[cur ^ 1][r][c4 * 4], &kbase[(size_t)(cn + r) * 384 + c4 * 4]);
                cp16(&Vs[cur ^ 1][r][c4 * 4], &vbase[(size_t)(cn + r) * 384 + c4 * 4]);
            }
            CP_COMMIT();
            CP_WAIT(1);
        } else {
            CP_WAIT(0);
        }
        __syncthreads();
        int c0k = kt * 64;
        // S = Q @ K^T : per-warp 16x64; cs doubles as P storage (in-place)
        float cs[8][4] = {};
        #pragma unroll
        for (int ks = 0; ks < 4; ks++) {
            int k0 = ks * 8;
            #pragma unroll
            for (int nt = 0; nt < 8; nt++) {
                unsigned bb[2];
                bb[0] = __float_as_uint(Ks[cur][nt * 8 + gid][k0 + tig]);
                bb[1] = __float_as_uint(Ks[cur][nt * 8 + gid][k0 + tig + 4]);
                mma_tf32(cs[nt], qa[ks], bb);
            }
        }
        // mask (int2), in place
        const int2* mr0 = (const int2*)(mbase + (size_t)(w * 16 + gid) * SS + c0k);
        const int2* mr1 = (const int2*)(mbase + (size_t)(w * 16 + gid + 8) * SS + c0k);
        #pragma unroll
        for (int nt = 0; nt < 8; nt++) {
            int2 m0v = mr0[nt * 4 + tig];
            int2 m1v = mr1[nt * 4 + tig];
            if (m0v.x == 0) cs[nt][0] = -1e9f;
            if (m0v.y == 0) cs[nt][1] = -1e9f;
            if (m1v.x == 0) cs[nt][2] = -1e9f;
            if (m1v.y == 0) cs[nt][3] = -1e9f;
        }
        // online softmax, in place on cs
        float t0 = cs[0][0], t1 = cs[0][2];
        #pragma unroll
        for (int nt = 0; nt < 8; nt++) {
            t0 = fmaxf(t0, fmaxf(cs[nt][0], cs[nt][1]));
            t1 = fmaxf(t1, fmaxf(cs[nt][2], cs[nt][3]));
        }
        t0 = fmaxf(t0, __shfl_xor_sync(0xffffffffu, t0, 1));
        t0 = fmaxf(t0, __shfl_xor_sync(0xffffffffu, t0, 2));
        t1 = fmaxf(t1, __shfl_xor_sync(0xffffffffu, t1, 1));
        t1 = fmaxf(t1, __shfl_xor_sync(0xffffffffu, t1, 2));
        float mn0 = fmaxf(m0, t0), mn1 = fmaxf(m1, t1);
        float corr0 = fast_exp(m0 - mn0), corr1 = fast_exp(m1 - mn1);
        float ps0 = 0.0f, ps1 = 0.0f;
        #pragma unroll
        for (int nt = 0; nt < 8; nt++) {
            cs[nt][0] = fast_exp(cs[nt][0] - mn0);
            cs[nt][1] = fast_exp(cs[nt][1] - mn0);
            cs[nt][2] = fast_exp(cs[nt][2] - mn1);
            cs[nt][3] = fast_exp(cs[nt][3] - mn1);
            ps0 += cs[nt][0] + cs[nt][1];
            ps1 += cs[nt][2] + cs[nt][3];
        }
        ps0 += __shfl_xor_sync(0xffffffffu, ps0, 1);
        ps0 += __shfl_xor_sync(0xffffffffu, ps0, 2);
        ps1 += __shfl_xor_sync(0xffffffffu, ps1, 1);
        ps1 += __shfl_xor_sync(0xffffffffu, ps1, 2);
        l0 = l0 * corr0 + ps0; m0 = mn0;
        l1 = l1 * corr1 + ps1; m1 = mn1;
        #pragma unroll
        for (int nt = 0; nt < 4; nt++) {
            o_acc[nt][0] *= corr0; o_acc[nt][1] *= corr0;
            o_acc[nt][2] *= corr1; o_acc[nt][3] *= corr1;
        }
        // O += P @ V : P fragments via intra-quad shuffles on cs, raw bits
        #pragma unroll
        for (int ks = 0; ks < 8; ks++) {
            float lo0 = __shfl_sync(0xffffffffu, cs[ks][0], src0);
            float hi0 = __shfl_sync(0xffffffffu, cs[ks][1], src0);
            float lo1 = __shfl_sync(0xffffffffu, cs[ks][2], src0);
            float hi1 = __shfl_sync(0xffffffffu, cs[ks][3], src0);
            float lo2 = __shfl_sync(0xffffffffu, cs[ks][0], src2);
            float hi2 = __shfl_sync(0xffffffffu, cs[ks][1], src2);
            float lo3 = __shfl_sync(0xffffffffu, cs[ks][2], src2);
            float hi3 = __shfl_sync(0xffffffffu, cs[ks][3], src2);
            unsigned a[4];
            a[0] = __float_as_uint(oddc ? hi0 : lo0);
            a[1] = __float_as_uint(oddc ? hi1 : lo1);
            a[2] = __float_as_uint(oddc ? hi2 : lo2);
            a[3] = __float_as_uint(oddc ? hi3 : lo3);
            int k0 = ks * 8;
            #pragma unroll
            for (int nt = 0; nt < 4; nt++) {
                unsigned bb[2];
                bb[0] = __float_as_uint(Vs[cur][k0 + tig    ][nt * 8 + gid]);
                bb[1] = __float_as_uint(Vs[cur][k0 + tig + 4][nt * 8 + gid]);
                mma_tf32(o_acc[nt], a, bb);
            }
        }
        __syncthreads();
    }
    // epilogue
    float inv0 = __fdividef(1.0f, l0);
    float inv1 = __fdividef(1.0f, l1);
    #pragma unroll
    for (int nt = 0; nt < 4; nt++) {
        int col = h * 32 + nt * 8 + tig * 2;
        size_t row0 = (size_t)(b * SS + q0 + w * 16 + gid);
        float2 v0; v0.x = o_acc[nt][0] * inv0; v0.y = o_acc[nt][1] * inv0;
        *(float2*)&o[row0 * HH + col] = v0;
        float2 v1; v1.x = o_acc[nt][2] * inv1; v1.y = o_acc[nt][3] * inv1;
        *(float2*)&o[(row0 + 8) * HH + col] = v1;
    }
}

// ---------------- neighbor proj helper -------------------------------------
__device__ __forceinline__ void proj64(const float* ln, const float* __restrict__ W,
                                       const float* __restrict__ bias, float* out, int tid) {
    int c2 = (tid & 63) * 2;
    int q4 = tid >> 6;
    int r0 = q4 * 16;
    float acc0[16], acc1[16];
    float bv0 = bias[c2], bv1 = bias[c2 + 1];
    #pragma unroll
    for (int i = 0; i < 16; i++) { acc0[i] = bv0; acc1[i] = bv1; }
    #pragma unroll 4
    for (int hh = 0; hh < HH; hh++) {
        float2 w = *(const float2*)&W[hh * HH + c2];
        #pragma unroll
        for (int i = 0; i < 16; i++) {
            float a = ln[(r0 + i) * 129 + hh];
            acc0[i] += a * w.x;
            acc1[i] += a * w.y;
        }
    }
    #pragma unroll
    for (int i = 0; i < 16; i++) {
        out[(r0 + i) * 129 + c2] = acc0[i];
        out[(r0 + i) * 129 + c2 + 1] = acc1[i];
    }
}

// ---------------- neighbor attention (last-token only) + fused Bn ----------
__global__ void neigh_kernel(const float* __restrict__ neighs, const int* __restrict__ nmask,
                             const float* __restrict__ wq, const float* __restrict__ bq,
                             const float* __restrict__ wk, const float* __restrict__ bk,
                             const float* __restrict__ wv, const float* __restrict__ bv,
                             const float* __restrict__ wo, const float* __restrict__ bo,
                             const float* __restrict__ g1, const float* __restrict__ b1,
                             const float* __restrict__ Wnc,
                             float* __restrict__ xnei, float* __restrict__ Bn) {
    extern __shared__ float sh[];
    float* ln  = sh;
    float* kv  = ln + 64 * 129;
    float* qv  = kv + 64 * 129;
    float* osh = qv + 128;
    float* sc  = osh + 128;
    int tid = threadIdx.x;
    int nb = blockIdx.x;
    int n = nb / BB, b = nb % BB;
    const float* base = neighs + (size_t)nb * SNN * HH;
    for (int idx = tid; idx < SNN * HH; idx += 256) {
        int r = idx >> 7, c = idx & 127;
        ln[r * 129 + c] = base[idx];
    }
    __syncthreads();
    {
        int warp = tid >> 5, lane = tid & 31;
        for (int r = warp; r < SNN; r += 8) {
            float s = 0.0f, s2 = 0.0f;
            #pragma unroll
            for (int c = lane; c < HH; c += 32) {
                float v = ln[r * 129 + c];
                s += v; s2 += v * v;
            }
            #pragma unroll
            for (int o = 16; o > 0; o >>= 1) {
                s  += __shfl_xor_sync(0xffffffffu, s, o);
                s2 += __shfl_xor_sync(0xffffffffu, s2, o);
            }
            float mean = s * (1.0f / HH);
            float var = s2 * (1.0f / HH) - mean * mean;
            float rs = rsqrtf(var + 1e-6f);
            #pragma unroll
            for (int c = lane; c < HH; c += 32) {
                float v = ln[r * 129 + c];
                ln[r * 129 + c] = (v - mean) * rs * g1[c] + b1[c];
            }
        }
    }
    __syncthreads();
    proj64(ln, wk, bk, kv, tid);
    if (tid < HH) {
        float a = bq[tid];
        #pragma unroll 4
        for (int hh = 0; hh < HH; hh++) a += ln[63 * 129 + hh] * wq[hh * HH + tid];
        qv[tid] = a;
    }
    __syncthreads();
    {
        int head = tid >> 6, j = tid & 63;
        float s = 0.0f;
        #pragma unroll
        for (int d = 0; d < DD; d++) s += qv[head * DD + d] * kv[j * 129 + head * DD + d];
        s *= 0.17677669529663687f;
        int mval = nmask[((size_t)nb * SNN + (SNN - 1)) * SNN + j];
        if (mval == 0) s = -1e9f;
        sc[head * 64 + j] = s;
    }
    __syncthreads();
    if (tid < 4) {
        float m = -1e30f;
        for (int j = 0; j < 64; j++) m = fmaxf(m, sc[tid * 64 + j]);
        float l = 0.0f;
        for (int j = 0; j < 64; j++) {
            float p = fast_exp(sc[tid * 64 + j] - m);
            sc[tid * 64 + j] = p; l += p;
        }
        float inv = 1.0f / l;
        for (int j = 0; j < 64; j++) sc[tid * 64 + j] *= inv;
    }
    __syncthreads();
    proj64(ln, wv, bv, kv, tid);
    __syncthreads();
    if (tid < HH) {
        int head = tid >> 5;
        float o = 0.0f;
        #pragma unroll 4
        for (int j = 0; j < 64; j++) o += sc[head * 64 + j] * kv[j * 129 + tid];
        osh[tid] = o;
    }
    __syncthreads();
    if (tid < HH) {
        float r = bo[tid] + base[(SNN - 1) * HH + tid];
        #pragma unroll 4
        for (int hh = 0; hh < HH; hh++) r += osh[hh] * wo[hh * HH + tid];
        xnei[((size_t)b * NN + n) * HH + tid] = r;
        qv[tid] = r;                            // stash for Bn pass
    }
    __syncthreads();
    // fused Bn = xnei_row @ Wnc : 256 threads, split K in halves
    {
        int col = tid & 127;
        int kh = (tid >> 7) * 64;
        float acc = 0.0f;
        #pragma unroll 4
        for (int k = 0; k < 64; k++)
            acc += qv[kh + k] * Wnc[(size_t)(kh + k) * HH + col];
        sc[tid] = acc;
    }
    __syncthreads();
    if (tid < HH)
        Bn[((size_t)b * NN + n) * HH + tid] = sc[tid] + sc[tid + 128];
}

// ---------------- attention-pooling kernel (tf32 mma, B-scaled) ------------
__global__ __launch_bounds__(256) void au_kernel(
        const float* __restrict__ x2, const float* __restrict__ Ag,
        const float* __restrict__ Bng, const float* __restrict__ xnei,
        const float* __restrict__ au_w1, const float* __restrict__ au_w2,
        const float* __restrict__ au_b2, float* __restrict__ out) {
    extern __shared__ float sh[];
    float* x2s    = sh;                  // 64*132 tf32
    float* W2s    = x2s + 64 * 132;      // 128*132 tf32
    float* xns    = W2s + 128 * 132;     // 16*128 fp32
    float* logits = xns + 2048;          // 64*16
    int tid = threadIdx.x;
    int b = blockIdx.y;
    int s0 = blockIdx.x * 64;
    int w = tid >> 5, lane = tid & 31;
    int gid = lane >> 2, tig = lane & 3;
    int wn = w * 16;
    for (int idx = tid; idx < HH * HH; idx += 256) {
        int k = idx >> 7, nn = idx & 127;
        W2s[k * 132 + nn] = f2tf_f(au_w1[HH * HH + idx]);
    }
    for (int idx = tid; idx < 64 * HH; idx += 256) {
        int r = idx >> 7, cc = idx & 127;
        x2s[r * 132 + cc] = f2tf_f(x2[((size_t)b * SS + s0 + r) * HH + cc]);
    }
    for (int idx = tid; idx < NN * HH; idx += 256) xns[idx] = xnei[(size_t)b * NN * HH + idx];
    for (int idx = tid; idx < 64 * 16; idx += 256) logits[idx] = 0.0f;
    int colv[4];
    float w2r[4];
    #pragma unroll
    for (int q = 0; q < 4; q++) {
        colv[q] = wn + (q >> 1) * 8 + tig * 2 + (q & 1);
        w2r[q] = au_w2[colv[q]];
    }
    float Areg[8][4];
    #pragma unroll
    for (int mt = 0; mt < 4; mt++)
        #pragma unroll
        for (int hh = 0; hh < 2; hh++) {
            int r = mt * 16 + gid + hh * 8;
            #pragma unroll
            for (int q = 0; q < 4; q++)
                Areg[mt * 2 + hh][q] = Ag[((size_t)b * SS + s0 + r) * HH + colv[q]];
        }
    __syncthreads();
    for (int n = 0; n < NN; n++) {
        const float* xnp = xns + n * 128;
        float c[4][2][4] = {};
        #pragma unroll
        for (int ks = 0; ks < 16; ks++) {
            int k0 = ks * 8;
            float xn0 = xnp[k0 + tig];
            float xn4 = xnp[k0 + tig + 4];
            unsigned bfr[2][2];
            #pragma unroll
            for (int nt = 0; nt < 2; nt++) {
                bfr[nt][0] = f2tf(W2s[(k0 + tig) * 132 + wn + nt * 8 + gid] * xn0);
                bfr[nt][1] = f2tf(W2s[(k0 + tig + 4) * 132 + wn + nt * 8 + gid] * xn4);
            }
            #pragma unroll
            for (int mt = 0; mt < 4; mt++) {
                unsigned a[4];
                a[0] = __float_as_uint(x2s[(mt * 16 + gid) * 132 + k0 + tig]);
                a[1] = __float_as_uint(x2s[(mt * 16 + gid + 8) * 132 + k0 + tig]);
                a[2] = __float_as_uint(x2s[(mt * 16 + gid) * 132 + k0 + tig + 4]);
                a[3] = __float_as_uint(x2s[(mt * 16 + gid + 8) * 132 + k0 + tig + 4]);
                mma_tf32(c[mt][0], a, bfr[0]);
                mma_tf32(c[mt][1], a, bfr[1]);
            }
        }
        float BnR[4];
        #pragma unroll
        for (int q = 0; q < 4; q++)
            BnR[q] = Bng[((size_t)b * NN + n) * HH + colv[q]];
        #pragma unroll
        for (int mt = 0; mt < 4; mt++) {
            float part0 = 0.0f, part1 = 0.0f;
            #pragma unroll
            for (int nt = 0; nt < 2; nt++)
                #pragma unroll
                for (int cc = 0; cc < 2; cc++) {
                    int q = nt * 2 + cc;
                    float v0 = c[mt][nt][cc]     + Areg[mt * 2][q]     + BnR[q];
                    float v1 = c[mt][nt][2 + cc] + Areg[mt * 2 + 1][q] + BnR[q];
                    part0 += fmaxf(v0, 0.0f) * w2r[q];
                    part1 += fmaxf(v1, 0.0f) * w2r[q];
                }
            part0 += __shfl_xor_sync(0xffffffffu, part0, 1);
            part0 += __shfl_xor_sync(0xffffffffu, part0, 2);
            part1 += __shfl_xor_sync(0xffffffffu, part1, 1);
            part1 += __shfl_xor_sync(0xffffffffu, part1, 2);
            if (tig == 0) {
                atomicAdd(&logits[(mt * 16 + gid) * 16 + n], part0);
                atomicAdd(&logits[(mt * 16 + gid + 8) * 16 + n], part1);
            }
        }
    }
    __syncthreads();
    if (tid < 64) {
        float m = -1e30f;
        #pragma unroll
        for (int n = 0; n < NN; n++) m = fmaxf(m, logits[tid * 16 + n]);
        float l = 0.0f;
        #pragma unroll
        for (int n = 0; n < NN; n++) {
            float p = fast_exp(logits[tid * 16 + n] - m);
            logits[tid * 16 + n] = p; l += p;
        }
        float inv = __fdividef(1.0f, l);
        #pragma unroll
        for (int n = 0; n < NN; n++) logits[tid * 16 + n] *= inv;
    }
    __syncthreads();
    for (int idx = tid; idx < 64 * HH; idx += 256) {
        int r = idx >> 7, cc = idx & 127;
        float o = x2[((size_t)b * SS + s0 + r) * HH + cc];
        #pragma unroll
        for (int n = 0; n < NN; n++) o += logits[r * 16 + n] * xns[n * HH + cc];
        out[((size_t)b * SS + s0 + r) * HH + cc] = o;
    }
}

// ---------------- launch ----------------
extern "C" void kernel_launch(void* const* d_in, const int* in_sizes, int n_in,
                              void* d_out, int out_size) {
    const float* x      = (const float*)d_in[0];
    const int*   mask   = (const int*)  d_in[1];
    const float* neighs = (const float*)d_in[2];
    const int*   nmask  = (const int*)  d_in[3];
    const float* wq = (const float*)d_in[4];  const float* bq = (const float*)d_in[5];
    const float* wk = (const float*)d_in[6];  const float* bk = (const float*)d_in[7];
    const float* wv = (const float*)d_in[8];  const float* bv = (const float*)d_in[9];
    const float* wo = (const float*)d_in[10]; const float* bo = (const float*)d_in[11];
    const float* ln1_g = (const float*)d_in[12]; const float* ln1_b = (const float*)d_in[13];
    const float* ln2_g = (const float*)d_in[14]; const float* ln2_b = (const float*)d_in[15];
    const float* ff_w1 = (const float*)d_in[16]; const float* ff_b1 = (const float*)d_in[17];
    const float* ff_w2 = (const float*)d_in[18]; const float* ff_b2 = (const float*)d_in[19];
    const float* au_w1 = (const float*)d_in[20]; const float* au_b1 = (const float*)d_in[21];
    const float* au_w2 = (const float*)d_in[22]; const float* au_b2 = (const float*)d_in[23];
    float* out = (float*)d_out;

    float *p_xn, *p_qkv, *p_attn, *p_x1, *p_h, *p_ffh, *p_x2, *p_A,
          *p_xnei, *p_Bn, *p_Wd, *p_Wnc, *p_Wqkv, *p_bqkv;
    cudaGetSymbolAddress((void**)&p_xn, g_xn);
    cudaGetSymbolAddress((void**)&p_qkv, g_qkv);
    cudaGetSymbolAddress((void**)&p_attn, g_attn);
    cudaGetSymbolAddress((void**)&p_x1, g_x1);
    cudaGetSymbolAddress((void**)&p_h, g_h);
    cudaGetSymbolAddress((void**)&p_ffh, g_ffh);
    cudaGetSymbolAddress((void**)&p_x2, g_x2);
    cudaGetSymbolAddress((void**)&p_A, g_A);
    cudaGetSymbolAddress((void**)&p_xnei, g_xnei);
    cudaGetSymbolAddress((void**)&p_Bn, g_Bn);
    cudaGetSymbolAddress((void**)&p_Wd, g_Wd);
    cudaGetSymbolAddress((void**)&p_Wnc, g_Wnc);
    cudaGetSymbolAddress((void**)&p_Wqkv, g_Wqkv);
    cudaGetSymbolAddress((void**)&p_bqkv, g_bqkv);

    const int neigh_shmem = (64 * 129 * 2 + 128 + 128 + 256) * 4;            // ~68 KB
    const int au_shmem = (64 * 132 + 128 * 132 + 2048 + 64 * 16) * 4;        // 113664 B
    cudaFuncSetAttribute(neigh_kernel, cudaFuncAttributeMaxDynamicSharedMemorySize, neigh_shmem);
    cudaFuncSetAttribute(au_kernel, cudaFuncAttributeMaxDynamicSharedMemorySize, au_shmem);

    // fork/join stream for the independent neighbor branch (capture-safe).
    // Stream/events are host objects (no device memory); not destroyed here
    // because destroying a capturing stream would invalidate graph capture.
    cudaStream_t s2;
    cudaStreamCreateWithFlags(&s2, cudaStreamNonBlocking);
    cudaEvent_t eFork, eJoin;
    cudaEventCreateWithFlags(&eFork, cudaEventDisableTiming);
    cudaEventCreateWithFlags(&eJoin, cudaEventDisableTiming);

    prep_kernel<<<192, 256>>>(au_w1, wq, wk, wv, bq, bk, bv, p_Wd, p_Wnc, p_Wqkv, p_bqkv);
    // fork: neigh branch depends only on prep (Wnc) + its own inputs
    cudaEventRecord(eFork, 0);
    cudaStreamWaitEvent(s2, eFork, 0);
    neigh_kernel<<<NN * BB, 256, neigh_shmem, s2>>>(neighs, nmask, wq, bq, wk, bk, wv, bv,
                                                    wo, bo, ln1_g, ln1_b, p_Wnc, p_xnei, p_Bn);
    cudaEventRecord(eJoin, s2);

    // main path
    ln_kernel<<<ROWS, 128>>>(x, ln1_g, ln1_b, p_xn);
    {
        dim3 g(384 / TBN, ROWS / TBM);
        sgemm_tc<<<g, 256>>>(p_xn, p_Wqkv, p_bqkv, nullptr, p_qkv, ROWS, HH, 384, 0);
    }
    attn_kernel<<<BB * NHEADS * 8, 128>>>(p_qkv, mask, p_attn);
    {
        dim3 g(1, ROWS / TBM);
        sgemm_tc<<<g, 256>>>(p_attn, wo, bo, x, p_x1, ROWS, HH, HH, 0);
    }
    ln_kernel<<<ROWS, 128>>>(p_x1, ln2_g, ln2_b, p_h);
    {
        dim3 g(FFD / TBN, ROWS / TBM);
        sgemm_tc<<<g, 256>>>(p_h, ff_w1, ff_b1, nullptr, p_ffh, ROWS, HH, FFD, 1);
    }
    {
        dim3 g(1, ROWS / TBM);
        sgemm_tc<<<g, 256>>>(p_ffh, ff_w2, ff_b2, p_x1, p_x2, ROWS, FFD, HH, 0);
    }
    {
        dim3 g(1, ROWS / TBM);
        sgemm_tc<<<g, 256>>>(p_x2, p_Wd, au_b1, nullptr, p_A, ROWS, HH, HH, 0);
    }
    // join: au needs xnei/Bn from the neigh branch
    cudaStreamWaitEvent(0, eJoin, 0);
    {
        dim3 g(SS / 64, BB);
        au_kernel<<<g, 256, au_shmem>>>(p_x2, p_A, p_Bn, p_xnei, au_w1, au_w2, au_b2, out);
    }
}

// round 14
// speedup vs baseline: 1.2784x; 1.0122x over previous
#include <cuda_runtime.h>
#include <cuda_bf16.h>
#include <math.h>

// Problem dims
#define BB 32
#define SS 512
#define HH 128
#define NHEADS 4
#define DD 32
#define FFD 512
#define NN 16
#define SNN 64
#define ROWS (BB*SS)          // 16384

// ---------------- static device scratch ----------------
__device__ float g_xn  [ROWS*HH];
__device__ float g_qkv [ROWS*384];
__device__ float g_attn[ROWS*HH];
__device__ float g_x1  [ROWS*HH];
__device__ float g_h   [ROWS*HH];
__device__ float g_ffh [ROWS*FFD];
__device__ float g_x2  [ROWS*HH];
__device__ float g_A   [ROWS*HH];
__device__ float g_xnei[BB*NN*HH];
__device__ float g_Bn  [BB*NN*HH];
__device__ float g_Wd  [HH*HH];
__device__ float g_Wnc [HH*HH];
__device__ float g_Wqkv[HH*384];
__device__ float g_bqkv[384];

// ---------------- tf32 / mma / cp.async helpers ----------------------------
__device__ __forceinline__ unsigned f2tf(float f) {
    unsigned r;
    asm("cvt.rna.tf32.f32 %0, %1;" : "=r"(r) : "f"(f));
    return r;
}
__device__ __forceinline__ float f2tf_f(float f) { return __uint_as_float(f2tf(f)); }

__device__ __forceinline__ void mma_tf32(float* c, const unsigned* a, const unsigned* b) {
    asm volatile(
        "mma.sync.aligned.m16n8k8.row.col.f32.tf32.tf32.f32 "
        "{%0,%1,%2,%3}, {%4,%5,%6,%7}, {%8,%9}, {%0,%1,%2,%3};"
        : "+f"(c[0]), "+f"(c[1]), "+f"(c[2]), "+f"(c[3])
        : "r"(a[0]), "r"(a[1]), "r"(a[2]), "r"(a[3]), "r"(b[0]), "r"(b[1]));
}

__device__ __forceinline__ void cp16(void* smem, const void* gmem) {
    unsigned s = (unsigned)__cvta_generic_to_shared(smem);
    asm volatile("cp.async.cg.shared.global [%0], [%1], 16;\n" :: "r"(s), "l"(gmem));
}
#define CP_COMMIT() asm volatile("cp.async.commit_group;\n" ::: "memory")
#define CP_WAIT(n)  asm volatile("cp.async.wait_group %0;\n" :: "n"(n) : "memory")

// ---------------- fast exp: FMA-pipe polynomial (no MUFU) ----------------
__device__ __forceinline__ float fast_exp(float x) {
    float z = x * 1.4426950408889634f;
    z = fminf(fmaxf(z, -126.0f), 126.0f);
    float t = z + 12582912.0f;
    int n = __float_as_int(t) - 0x4B400000;
    float f = z - (t - 12582912.0f);
    float p = 0.0013333558f;
    p = fmaf(p, f, 0.0096181291f);
    p = fmaf(p, f, 0.0555041087f);
    p = fmaf(p, f, 0.2402265070f);
    p = fmaf(p, f, 0.6931471806f);
    p = fmaf(p, f, 1.0f);
    return __int_as_float(__float_as_int(p) + (n << 23));
}

__device__ __forceinline__ float gelu_fast(float x) {
    float u = 0.7978845608028654f * (x + 0.044715f * x * x * x);
    float t = fast_exp(-2.0f * u);
    return __fdividef(x, 1.0f + t);
}

// ---------------- prep ------------------------------------------------------
__global__ void prep_kernel(const float* __restrict__ au_w1,
                            const float* __restrict__ wq, const float* __restrict__ wk,
                            const float* __restrict__ wv,
                            const float* __restrict__ bq, const float* __restrict__ bk,
                            const float* __restrict__ bv,
                            float* __restrict__ Wd, float* __restrict__ Wnc,
                            float* __restrict__ Wqkv, float* __restrict__ bqkv) {
    int idx = blockIdx.x * blockDim.x + threadIdx.x;
    if (idx < HH * HH) {
        int h = idx >> 7, j = idx & 127;
        float w1 = au_w1[h * HH + j];
        float w3 = au_w1[(256 + h) * HH + j];
        float w4 = au_w1[(384 + h) * HH + j];
        Wd[idx]  = w1 - w3;
        Wnc[idx] = w3 + w4;
    }
    if (idx < HH * 384) {
        int h = idx / 384, c = idx % 384;
        float v = (c < 128) ? wq[h * 128 + c]
                 : (c < 256) ? wk[h * 128 + (c - 128)]
                             : wv[h * 128 + (c - 256)];
        Wqkv[idx] = v;
    }
    if (idx < 384) {
        bqkv[idx] = (idx < 128) ? bq[idx] : (idx < 256) ? bk[idx - 128] : bv[idx - 256];
    }
}

// ---------------- layernorm ------------------------------------------------
__global__ void ln_kernel(const float* __restrict__ x, const float* __restrict__ g,
                          const float* __restrict__ b, float* __restrict__ y) {
    int row = blockIdx.x;
    int t = threadIdx.x;
    float v = x[(size_t)row * HH + t];
    float s = v, s2 = v * v;
    #pragma unroll
    for (int o = 16; o > 0; o >>= 1) {
        s  += __shfl_xor_sync(0xffffffffu, s, o);
        s2 += __shfl_xor_sync(0xffffffffu, s2, o);
    }
    __shared__ float ws[8];
    if ((t & 31) == 0) { ws[t >> 5] = s; ws[4 + (t >> 5)] = s2; }
    __syncthreads();
    s  = ws[0] + ws[1] + ws[2] + ws[3];
    s2 = ws[4] + ws[5] + ws[6] + ws[7];
    float mean = s * (1.0f / HH);
    float var = s2 * (1.0f / HH) - mean * mean;
    float rs = rsqrtf(var + 1e-6f);
    y[(size_t)row * HH + t] = (v - mean) * rs * g[t] + b[t];
}

// ---------------- TF32 tensor-core GEMM: cp.async double-buffered ----------
#define TBM 128
#define TBN 128
#define TBK 16
__device__ __forceinline__ void gemm_issue_tile(
    const float* __restrict__ A, const float* __restrict__ W,
    float (*As)[20], float (*Ws)[132],
    int bm, int bn, int K, int N, int k0, int tid) {
    #pragma unroll
    for (int l = 0; l < 2; l++) {
        int ch = l * 256 + tid;
        int ar = ch >> 2, ac = ch & 3;          // 128 rows x 4 chunks
        cp16(&As[ar][ac * 4], &A[(size_t)(bm + ar) * K + k0 + ac * 4]);
        int wr = ch >> 5, wc = ch & 31;         // 16 rows x 32 chunks
        cp16(&Ws[wr][wc * 4], &W[(size_t)(k0 + wr) * N + bn + wc * 4]);
    }
}

__global__ __launch_bounds__(256) void sgemm_tc(
    const float* __restrict__ A, const float* __restrict__ W,
    const float* __restrict__ bias, const float* __restrict__ res,
    float* __restrict__ C, int M, int K, int N, int act) {
    __shared__ float As[2][TBM][20];
    __shared__ float Ws[2][TBK][132];
    int bm = blockIdx.y * TBM, bn = blockIdx.x * TBN;
    int tid = threadIdx.x;
    int wid = tid >> 5, lane = tid & 31;
    int gid = lane >> 2, tig = lane & 3;
    int wm = (wid >> 2) * 64, wn = (wid & 3) * 32;
    gemm_issue_tile(A, W, As[0], Ws[0], bm, bn, K, N, 0, tid);
    CP_COMMIT();
    float c[4][4][4] = {};
    int nk = K / TBK;
    for (int kt = 0; kt < nk; kt++) {
        int cur = kt & 1;
        if (kt + 1 < nk) {
            gemm_issue_tile(A, W, As[cur ^ 1], Ws[cur ^ 1], bm, bn, K, N, (kt + 1) * TBK, tid);
            CP_COMMIT();
            CP_WAIT(1);
        } else {
            CP_WAIT(0);
        }
        __syncthreads();
        #pragma unroll
        for (int ks = 0; ks < 2; ks++) {
            int k0 = ks * 8;
            unsigned a[4][4], b[4][2];
            #pragma unroll
            for (int mt = 0; mt < 4; mt++) {
                a[mt][0] = __float_as_uint(As[cur][wm + mt * 16 + gid    ][k0 + tig]);
                a[mt][1] = __float_as_uint(As[cur][wm + mt * 16 + gid + 8][k0 + tig]);
                a[mt][2] = __float_as_uint(As[cur][wm + mt * 16 + gid    ][k0 + tig + 4]);
                a[mt][3] = __float_as_uint(As[cur][wm + mt * 16 + gid + 8][k0 + tig + 4]);
            }
            #pragma unroll
            for (int nt = 0; nt < 4; nt++) {
                b[nt][0] = __float_as_uint(Ws[cur][k0 + tig    ][wn + nt * 8 + gid]);
                b[nt][1] = __float_as_uint(Ws[cur][k0 + tig + 4][wn + nt * 8 + gid]);
            }
            #pragma unroll
            for (int mt = 0; mt < 4; mt++)
                #pragma unroll
                for (int nt = 0; nt < 4; nt++)
                    mma_tf32(c[mt][nt], a[mt], b[nt]);
        }
        __syncthreads();
    }
    // epilogue
    #pragma unroll
    for (int mt = 0; mt < 4; mt++) {
        #pragma unroll
        for (int nt = 0; nt < 4; nt++) {
            int col = bn + wn + nt * 8 + tig * 2;
            float b0 = bias ? bias[col] : 0.0f;
            float b1 = bias ? bias[col + 1] : 0.0f;
            #pragma unroll
            for (int hh = 0; hh < 2; hh++) {
                int row = bm + wm + mt * 16 + gid + hh * 8;
                float v0 = c[mt][nt][hh * 2 + 0] + b0;
                float v1 = c[mt][nt][hh * 2 + 1] + b1;
                if (act == 1) { v0 = gelu_fast(v0); v1 = gelu_fast(v1); }
                if (res) {
                    const float2 rv = *(const float2*)&res[(size_t)row * N + col];
                    v0 += rv.x; v1 += rv.y;
                }
                float2 ov; ov.x = v0; ov.y = v1;
                *(float2*)&C[(size_t)row * N + col] = ov;
            }
        }
    }
}

// ---------------- FF2 + A-GEMM fused: x2 = gelu_ffh@W2 + b2 + x1, A = x2@Wd + b1
// N=128 fixed; each block owns 128 full rows, so x2 tile is complete in-block.
__global__ __launch_bounds__(256) void ff2_fused(
    const float* __restrict__ A, const float* __restrict__ W,
    const float* __restrict__ bias, const float* __restrict__ res,
    float* __restrict__ C,
    const float* __restrict__ Wd, const float* __restrict__ b1v,
    float* __restrict__ Aout, int K) {
    extern __shared__ float sh[];
    float* AsB  = sh;                       // 2*128*20 = 5120
    float* WsB  = AsB + 2 * TBM * 20;       // 2*16*132 = 4224
    float* x2sh = WsB + 2 * TBK * 132;      // 128*132  = 16896
    const int N = 128;
    int bm = blockIdx.y * TBM;
    int tid = threadIdx.x;
    int wid = tid >> 5, lane = tid & 31;
    int gid = lane >> 2, tig = lane & 3;
    int wm = (wid >> 2) * 64, wn = (wid & 3) * 32;
    // ---- pass 1: x2 = act(A@W)+bias+res ----
    #pragma unroll
    for (int l = 0; l < 2; l++) {
        int ch = l * 256 + tid;
        int ar = ch >> 2, ac = ch & 3;
        cp16(&AsB[ar * 20 + ac * 4], &A[(size_t)(bm + ar) * K + ac * 4]);
        int wr = ch >> 5, wc = ch & 31;
        cp16(&WsB[wr * 132 + wc * 4], &W[(size_t)wr * N + wc * 4]);
    }
    CP_COMMIT();
    float c[4][4][4] = {};
    int nk = K / TBK;
    for (int kt = 0; kt < nk; kt++) {
        int cur = kt & 1;
        if (kt + 1 < nk) {
            int k0 = (kt + 1) * TBK;
            #pragma unroll
            for (int l = 0; l < 2; l++) {
                int ch = l * 256 + tid;
                int ar = ch >> 2, ac = ch & 3;
                cp16(&AsB[(cur ^ 1) * TBM * 20 + ar * 20 + ac * 4],
                     &A[(size_t)(bm + ar) * K + k0 + ac * 4]);
                int wr = ch >> 5, wc = ch & 31;
                cp16(&WsB[(cur ^ 1) * TBK * 132 + wr * 132 + wc * 4],
                     &W[(size_t)(k0 + wr) * N + wc * 4]);
            }
            CP_COMMIT();
            CP_WAIT(1);
        } else {
            CP_WAIT(0);
        }
        __syncthreads();
        const float* Asb = AsB + cur * TBM * 20;
        const float* Wsb = WsB + cur * TBK * 132;
        #pragma unroll
        for (int ks = 0; ks < 2; ks++) {
            int k0 = ks * 8;
            unsigned a[4][4], b[4][2];
            #pragma unroll
            for (int mt = 0; mt < 4; mt++) {
                a[mt][0] = __float_as_uint(Asb[(wm + mt * 16 + gid    ) * 20 + k0 + tig]);
                a[mt][1] = __float_as_uint(Asb[(wm + mt * 16 + gid + 8) * 20 + k0 + tig]);
                a[mt][2] = __float_as_uint(Asb[(wm + mt * 16 + gid    ) * 20 + k0 + tig + 4]);
                a[mt][3] = __float_as_uint(Asb[(wm + mt * 16 + gid + 8) * 20 + k0 + tig + 4]);
            }
            #pragma unroll
            for (int nt = 0; nt < 4; nt++) {
                b[nt][0] = __float_as_uint(Wsb[(k0 + tig    ) * 132 + wn + nt * 8 + gid]);
                b[nt][1] = __float_as_uint(Wsb[(k0 + tig + 4) * 132 + wn + nt * 8 + gid]);
            }
            #pragma unroll
            for (int mt = 0; mt < 4; mt++)
                #pragma unroll
                for (int nt = 0; nt < 4; nt++)
                    mma_tf32(c[mt][nt], a[mt], b[nt]);
        }
        __syncthreads();
    }
    // epilogue 1: write x2 to global + smem
    #pragma unroll
    for (int mt = 0; mt < 4; mt++) {
        #pragma unroll
        for (int nt = 0; nt < 4; nt++) {
            int col = wn + nt * 8 + tig * 2;
            float b0 = bias[col], b1_ = bias[col + 1];
            #pragma unroll
            for (int hh = 0; hh < 2; hh++) {
                int rloc = wm + mt * 16 + gid + hh * 8;
                int row = bm + rloc;
                float v0 = c[mt][nt][hh * 2 + 0] + b0;
                float v1 = c[mt][nt][hh * 2 + 1] + b1_;
                const float2 rv = *(const float2*)&res[(size_t)row * N + col];
                v0 += rv.x; v1 += rv.y;
                float2 ov; ov.x = v0; ov.y = v1;
                *(float2*)&C[(size_t)row * N + col] = ov;
                x2sh[rloc * 132 + col]     = v0;
                x2sh[rloc * 132 + col + 1] = v1;
            }
        }
    }
    // ---- pass 2: Aout = x2sh @ Wd + b1 (K=128) ----
    #pragma unroll
    for (int l = 0; l < 2; l++) {
        int ch = l * 256 + tid;
        int wr = ch >> 5, wc = ch & 31;
        cp16(&WsB[wr * 132 + wc * 4], &Wd[(size_t)wr * N + wc * 4]);
    }
    CP_COMMIT();
    __syncthreads();                       // x2sh visible to all
    float c2[4][4][4] = {};
    for (int kt = 0; kt < 8; kt++) {
        int cur = kt & 1;
        if (kt + 1 < 8) {
            int k0 = (kt + 1) * TBK;
            #pragma unroll
            for (int l = 0; l < 2; l++) {
                int ch = l * 256 + tid;
                int wr = ch >> 5, wc = ch & 31;
                cp16(&WsB[(cur ^ 1) * TBK * 132 + wr * 132 + wc * 4],
                     &Wd[(size_t)(k0 + wr) * N + wc * 4]);
            }
            CP_COMMIT();
            CP_WAIT(1);
        } else {
            CP_WAIT(0);
        }
        __syncthreads();
        const float* Wsb = WsB + cur * TBK * 132;
        int kb = kt * TBK;
        #pragma unroll
        for (int ks = 0; ks < 2; ks++) {
            int k0 = kb + ks * 8;
            unsigned a[4][4], b[4][2];
            #pragma unroll
            for (int mt = 0; mt < 4; mt++) {
                a[mt][0] = __float_as_uint(x2sh[(wm + mt * 16 + gid    ) * 132 + k0 + tig]);
                a[mt][1] = __float_as_uint(x2sh[(wm + mt * 16 + gid + 8) * 132 + k0 + tig]);
                a[mt][2] = __float_as_uint(x2sh[(wm + mt * 16 + gid    ) * 132 + k0 + tig + 4]);
                a[mt][3] = __float_as_uint(x2sh[(wm + mt * 16 + gid + 8) * 132 + k0 + tig + 4]);
            }
            #pragma unroll
            for (int nt = 0; nt < 4; nt++) {
                b[nt][0] = __float_as_uint(Wsb[(ks * 8 + tig    ) * 132 + wn + nt * 8 + gid]);
                b[nt][1] = __float_as_uint(Wsb[(ks * 8 + tig + 4) * 132 + wn + nt * 8 + gid]);
            }
            #pragma unroll
            for (int mt = 0; mt < 4; mt++)
                #pragma unroll
                for (int nt = 0; nt < 4; nt++)
                    mma_tf32(c2[mt][nt], a[mt], b[nt]);
        }
        __syncthreads();
    }
    // epilogue 2
    #pragma unroll
    for (int mt = 0; mt < 4; mt++) {
        #pragma unroll
        for (int nt = 0; nt < 4; nt++) {
            int col = wn + nt * 8 + tig * 2;
            float b0 = b1v[col], b1_ = b1v[col + 1];
            #pragma unroll
            for (int hh = 0; hh < 2; hh++) {
                int row = bm + wm + mt * 16 + gid + hh * 8;
                float2 ov;
                ov.x = c2[mt][nt][hh * 2 + 0] + b0;
                ov.y = c2[mt][nt][hh * 2 + 1] + b1_;
                *(float2*)&Aout[(size_t)row * N + col] = ov;
            }
        }
    }
}

// ---------------- flash attention: cp.async pipeline, Q in regs ------------
__global__ __launch_bounds__(128, 5) void attn_kernel(const float* __restrict__ qkv,
                                                      const int* __restrict__ mask,
                                                      float* __restrict__ o) {
    __shared__ float Ks[2][64][36];
    __shared__ float Vs[2][64][36];
    int blk = blockIdx.x;
    int qt = blk & 7, h = (blk >> 3) & 3, b = blk >> 5;
    int q0 = qt * 64;
    int tid = threadIdx.x;
    int w = tid >> 5, lane = tid & 31;
    int gid = lane >> 2, tig = lane & 3;
    const float* qbase = qkv + (size_t)(b * SS + q0) * 384 + h * 32;
    const float* kbase = qkv + (size_t)b * SS * 384 + 128 + h * 32;
    const float* vbase = qkv + (size_t)b * SS * 384 + 256 + h * 32;
    const float scale = 0.17677669529663687f;
    #pragma unroll
    for (int k = 0; k < 4; k++) {
        int idx = tid + k * 128;
        int r = idx >> 3, c4 = idx & 7;
        float4 v = *(const float4*)&qbase[(size_t)r * 384 + c4 * 4];
        v.x *= scale; v.y *= scale; v.z *= scale; v.w *= scale;
        *(float4*)&Ks[0][r][c4 * 4] = v;
    }
    __syncthreads();
    unsigned qa[4][4];
    #pragma unroll
    for (int ks = 0; ks < 4; ks++) {
        int k0 = ks * 8;
        qa[ks][0] = __float_as_uint(Ks[0][w * 16 + gid    ][k0 + tig]);
        qa[ks][1] = __float_as_uint(Ks[0][w * 16 + gid + 8][k0 + tig]);
        qa[ks][2] = __float_as_uint(Ks[0][w * 16 + gid    ][k0 + tig + 4]);
        qa[ks][3] = __float_as_uint(Ks[0][w * 16 + gid + 8][k0 + tig + 4]);
    }
    __syncthreads();
    #pragma unroll
    for (int k = 0; k < 4; k++) {
        int idx = tid + k * 128;
        int r = idx >> 3, c4 = idx & 7;
        cp16(&Ks[0][r][c4 * 4], &kbase[(size_t)r * 384 + c4 * 4]);
        cp16(&Vs[0][r][c4 * 4], &vbase[(size_t)r * 384 + c4 * 4]);
    }
    CP_COMMIT();
    float o_acc[4][4] = {};
    float m0 = -1e30f, l0 = 0.0f, m1 = -1e30f, l1 = 0.0f;
    const int* mbase = mask + (size_t)b * SS * SS + (size_t)q0 * SS;
    int src0 = (lane & ~3) + (tig >> 1);
    int src2 = src0 + 2;
    bool oddc = (tig & 1) != 0;
    for (int kt = 0; kt < 8; kt++) {
        int cur = kt & 1;
        if (kt + 1 < 8) {
            int cn = (kt + 1) * 64;
            #pragma unroll
            for (int k = 0; k < 4; k++) {
                int idx = tid + k * 128;
                int r = idx >> 3, c4 = idx & 7;
                cp16(&Ks[cur ^ 1][r][c4 * 4], &kbase[(size_t)(cn + r) * 384 + c4 * 4]);
                cp16(&Vs[cur ^ 1][r][c4 * 4], &vbase[(size_t)(cn + r) * 384 + c4 * 4]);
            }
            CP_COMMIT();
            CP_WAIT(1);
        } else {
            CP_WAIT(0);
        }
        __syncthreads();
        int c0k = kt * 64;
        float cs[8][4] = {};
        #pragma unroll
        for (int ks = 0; ks < 4; ks++) {
            int k0 = ks * 8;
            #pragma unroll
            for (int nt = 0; nt < 8; nt++) {
                unsigned bb[2];
                bb[0] = __float_as_uint(Ks[cur][nt * 8 + gid][k0 + tig]);
                bb[1] = __float_as_uint(Ks[cur][nt * 8 + gid][k0 + tig + 4]);
                mma_tf32(cs[nt], qa[ks], bb);
            }
        }
        const int2* mr0 = (const int2*)(mbase + (size_t)(w * 16 + gid) * SS + c0k);
        const int2* mr1 = (const int2*)(mbase + (size_t)(w * 16 + gid + 8) * SS + c0k);
        #pragma unroll
        for (int nt = 0; nt < 8; nt++) {
            int2 m0v = mr0[nt * 4 + tig];
            int2 m1v = mr1[nt * 4 + tig];
            if (m0v.x == 0) cs[nt][0] = -1e9f;
            if (m0v.y == 0) cs[nt][1] = -1e9f;
            if (m1v.x == 0) cs[nt][2] = -1e9f;
            if (m1v.y == 0) cs[nt][3] = -1e9f;
        }
        float t0 = cs[0][0], t1 = cs[0][2];
        #pragma unroll
        for (int nt = 0; nt < 8; nt++) {
            t0 = fmaxf(t0, fmaxf(cs[nt][0], cs[nt][1]));
            t1 = fmaxf(t1, fmaxf(cs[nt][2], cs[nt][3]));
        }
        t0 = fmaxf(t0, __shfl_xor_sync(0xffffffffu, t0, 1));
        t0 = fmaxf(t0, __shfl_xor_sync(0xffffffffu, t0, 2));
        t1 = fmaxf(t1, __shfl_xor_sync(0xffffffffu, t1, 1));
        t1 = fmaxf(t1, __shfl_xor_sync(0xffffffffu, t1, 2));
        float mn0 = fmaxf(m0, t0), mn1 = fmaxf(m1, t1);
        float corr0 = fast_exp(m0 - mn0), corr1 = fast_exp(m1 - mn1);
        float ps0 = 0.0f, ps1 = 0.0f;
        #pragma unroll
        for (int nt = 0; nt < 8; nt++) {
            cs[nt][0] = fast_exp(cs[nt][0] - mn0);
            cs[nt][1] = fast_exp(cs[nt][1] - mn0);
            cs[nt][2] = fast_exp(cs[nt][2] - mn1);
            cs[nt][3] = fast_exp(cs[nt][3] - mn1);
            ps0 += cs[nt][0] + cs[nt][1];
            ps1 += cs[nt][2] + cs[nt][3];
        }
        ps0 += __shfl_xor_sync(0xffffffffu, ps0, 1);
        ps0 += __shfl_xor_sync(0xffffffffu, ps0, 2);
        ps1 += __shfl_xor_sync(0xffffffffu, ps1, 1);
        ps1 += __shfl_xor_sync(0xffffffffu, ps1, 2);
        l0 = l0 * corr0 + ps0; m0 = mn0;
        l1 = l1 * corr1 + ps1; m1 = mn1;
        #pragma unroll
        for (int nt = 0; nt < 4; nt++) {
            o_acc[nt][0] *= corr0; o_acc[nt][1] *= corr0;
            o_acc[nt][2] *= corr1; o_acc[nt][3] *= corr1;
        }
        #pragma unroll
        for (int ks = 0; ks < 8; ks++) {
            float lo0 = __shfl_sync(0xffffffffu, cs[ks][0], src0);
            float hi0 = __shfl_sync(0xffffffffu, cs[ks][1], src0);
            float lo1 = __shfl_sync(0xffffffffu, cs[ks][2], src0);
            float hi1 = __shfl_sync(0xffffffffu, cs[ks][3], src0);
            float lo2 = __shfl_sync(0xffffffffu, cs[ks][0], src2);
            float hi2 = __shfl_sync(0xffffffffu, cs[ks][1], src2);
            float lo3 = __shfl_sync(0xffffffffu, cs[ks][2], src2);
            float hi3 = __shfl_sync(0xffffffffu, cs[ks][3], src2);
            unsigned a[4];
            a[0] = __float_as_uint(oddc ? hi0 : lo0);
            a[1] = __float_as_uint(oddc ? hi1 : lo1);
            a[2] = __float_as_uint(oddc ? hi2 : lo2);
            a[3] = __float_as_uint(oddc ? hi3 : lo3);
            int k0 = ks * 8;
            #pragma unroll
            for (int nt = 0; nt < 4; nt++) {
                unsigned bb[2];
                bb[0] = __float_as_uint(Vs[cur][k0 + tig    ][nt * 8 + gid]);
                bb[1] = __float_as_uint(Vs[cur][k0 + tig + 4][nt * 8 + gid]);
                mma_tf32(o_acc[nt], a, bb);
            }
        }
        __syncthreads();
    }
    float inv0 = __fdividef(1.0f, l0);
    float inv1 = __fdividef(1.0f, l1);
    #pragma unroll
    for (int nt = 0; nt < 4; nt++) {
        int col = h * 32 + nt * 8 + tig * 2;
        size_t row0 = (size_t)(b * SS + q0 + w * 16 + gid);
        float2 v0; v0.x = o_acc[nt][0] * inv0; v0.y = o_acc[nt][1] * inv0;
        *(float2*)&o[row0 * HH + col] = v0;
        float2 v1; v1.x = o_acc[nt][2] * inv1; v1.y = o_acc[nt][3] * inv1;
        *(float2*)&o[(row0 + 8) * HH + col] = v1;
    }
}

// ---------------- neighbor proj helper -------------------------------------
__device__ __forceinline__ void proj64(const float* ln, const float* __restrict__ W,
                                       const float* __restrict__ bias, float* out, int tid) {
    int c2 = (tid & 63) * 2;
    int q4 = tid >> 6;
    int r0 = q4 * 16;
    float acc0[16], acc1[16];
    float bv0 = bias[c2], bv1 = bias[c2 + 1];
    #pragma unroll
    for (int i = 0; i < 16; i++) { acc0[i] = bv0; acc1[i] = bv1; }
    #pragma unroll 4
    for (int hh = 0; hh < HH; hh++) {
        float2 w = *(const float2*)&W[hh * HH + c2];
        #pragma unroll
        for (int i = 0; i < 16; i++) {
            float a = ln[(r0 + i) * 129 + hh];
            acc0[i] += a * w.x;
            acc1[i] += a * w.y;
        }
    }
    #pragma unroll
    for (int i = 0; i < 16; i++) {
        out[(r0 + i) * 129 + c2] = acc0[i];
        out[(r0 + i) * 129 + c2 + 1] = acc1[i];
    }
}

// ---------------- neighbor attention (last-token only) + fused Bn ----------
__global__ void neigh_kernel(const float* __restrict__ neighs, const int* __restrict__ nmask,
                             const float* __restrict__ wq, const float* __restrict__ bq,
                             const float* __restrict__ wk, const float* __restrict__ bk,
                             const float* __restrict__ wv, const float* __restrict__ bv,
                             const float* __restrict__ wo, const float* __restrict__ bo,
                             const float* __restrict__ g1, const float* __restrict__ b1,
                             const float* __restrict__ Wnc,
                             float* __restrict__ xnei, float* __restrict__ Bn) {
    extern __shared__ float sh[];
    float* ln  = sh;
    float* kv  = ln + 64 * 129;
    float* qv  = kv + 64 * 129;
    float* osh = qv + 128;
    float* sc  = osh + 128;
    int tid = threadIdx.x;
    int nb = blockIdx.x;
    int n = nb / BB, b = nb % BB;
    const float* base = neighs + (size_t)nb * SNN * HH;
    for (int idx = tid; idx < SNN * HH; idx += 256) {
        int r = idx >> 7, c = idx & 127;
        ln[r * 129 + c] = base[idx];
    }
    __syncthreads();
    {
        int warp = tid >> 5, lane = tid & 31;
        for (int r = warp; r < SNN; r += 8) {
            float s = 0.0f, s2 = 0.0f;
            #pragma unroll
            for (int c = lane; c < HH; c += 32) {
                float v = ln[r * 129 + c];
                s += v; s2 += v * v;
            }
            #pragma unroll
            for (int o = 16; o > 0; o >>= 1) {
                s  += __shfl_xor_sync(0xffffffffu, s, o);
                s2 += __shfl_xor_sync(0xffffffffu, s2, o);
            }
            float mean = s * (1.0f / HH);
            float var = s2 * (1.0f / HH) - mean * mean;
            float rs = rsqrtf(var + 1e-6f);
            #pragma unroll
            for (int c = lane; c < HH; c += 32) {
                float v = ln[r * 129 + c];
                ln[r * 129 + c] = (v - mean) * rs * g1[c] + b1[c];
            }
        }
    }
    __syncthreads();
    proj64(ln, wk, bk, kv, tid);
    if (tid < HH) {
        float a = bq[tid];
        #pragma unroll 4
        for (int hh = 0; hh < HH; hh++) a += ln[63 * 129 + hh] * wq[hh * HH + tid];
        qv[tid] = a;
    }
    __syncthreads();
    {
        int head = tid >> 6, j = tid & 63;
        float s = 0.0f;
        #pragma unroll
        for (int d = 0; d < DD; d++) s += qv[head * DD + d] * kv[j * 129 + head * DD + d];
        s *= 0.17677669529663687f;
        int mval = nmask[((size_t)nb * SNN + (SNN - 1)) * SNN + j];
        if (mval == 0) s = -1e9f;
        sc[head * 64 + j] = s;
    }
    __syncthreads();
    if (tid < 4) {
        float m = -1e30f;
        for (int j = 0; j < 64; j++) m = fmaxf(m, sc[tid * 64 + j]);
        float l = 0.0f;
        for (int j = 0; j < 64; j++) {
            float p = fast_exp(sc[tid * 64 + j] - m);
            sc[tid * 64 + j] = p; l += p;
        }
        float inv = 1.0f / l;
        for (int j = 0; j < 64; j++) sc[tid * 64 + j] *= inv;
    }
    __syncthreads();
    proj64(ln, wv, bv, kv, tid);
    __syncthreads();
    if (tid < HH) {
        int head = tid >> 5;
        float o = 0.0f;
        #pragma unroll 4
        for (int j = 0; j < 64; j++) o += sc[head * 64 + j] * kv[j * 129 + tid];
        osh[tid] = o;
    }
    __syncthreads();
    if (tid < HH) {
        float r = bo[tid] + base[(SNN - 1) * HH + tid];
        #pragma unroll 4
        for (int hh = 0; hh < HH; hh++) r += osh[hh] * wo[hh * HH + tid];
        xnei[((size_t)b * NN + n) * HH + tid] = r;
        qv[tid] = r;                            // stash for Bn pass
    }
    __syncthreads();
    {
        int col = tid & 127;
        int kh = (tid >> 7) * 64;
        float acc = 0.0f;
        #pragma unroll 4
        for (int k = 0; k < 64; k++)
            acc += qv[kh + k] * Wnc[(size_t)(kh + k) * HH + col];
        sc[tid] = acc;
    }
    __syncthreads();
    if (tid < HH)
        Bn[((size_t)b * NN + n) * HH + tid] = sc[tid] + sc[tid + 128];
}

// ---------------- attention-pooling kernel (tf32 mma, B-scaled) ------------
__global__ __launch_bounds__(256) void au_kernel(
        const float* __restrict__ x2, const float* __restrict__ Ag,
        const float* __restrict__ Bng, const float* __restrict__ xnei,
        const float* __restrict__ au_w1, const float* __restrict__ au_w2,
        const float* __restrict__ au_b2, float* __restrict__ out) {
    extern __shared__ float sh[];
    float* x2s    = sh;                  // 64*132 tf32
    float* W2s    = x2s + 64 * 132;      // 128*132 tf32
    float* xns    = W2s + 128 * 132;     // 16*128 fp32
    float* logits = xns + 2048;          // 64*16
    int tid = threadIdx.x;
    int b = blockIdx.y;
    int s0 = blockIdx.x * 64;
    int w = tid >> 5, lane = tid & 31;
    int gid = lane >> 2, tig = lane & 3;
    int wn = w * 16;
    for (int idx = tid; idx < HH * HH; idx += 256) {
        int k = idx >> 7, nn = idx & 127;
        W2s[k * 132 + nn] = f2tf_f(au_w1[HH * HH + idx]);
    }
    for (int idx = tid; idx < 64 * HH; idx += 256) {
        int r = idx >> 7, cc = idx & 127;
        x2s[r * 132 + cc] = f2tf_f(x2[((size_t)b * SS + s0 + r) * HH + cc]);
    }
    for (int idx = tid; idx < NN * HH; idx += 256) xns[idx] = xnei[(size_t)b * NN * HH + idx];
    for (int idx = tid; idx < 64 * 16; idx += 256) logits[idx] = 0.0f;
    int colv[4];
    float w2r[4];
    #pragma unroll
    for (int q = 0; q < 4; q++) {
        colv[q] = wn + (q >> 1) * 8 + tig * 2 + (q & 1);
        w2r[q] = au_w2[colv[q]];
    }
    float Areg[8][4];
    #pragma unroll
    for (int mt = 0; mt < 4; mt++)
        #pragma unroll
        for (int hh = 0; hh < 2; hh++) {
            int r = mt * 16 + gid + hh * 8;
            #pragma unroll
            for (int q = 0; q < 4; q++)
                Areg[mt * 2 + hh][q] = Ag[((size_t)b * SS + s0 + r) * HH + colv[q]];
        }
    __syncthreads();
    for (int n = 0; n < NN; n++) {
        const float* xnp = xns + n * 128;
        float c[4][2][4] = {};
        #pragma unroll
        for (int ks = 0; ks < 16; ks++) {
            int k0 = ks * 8;
            float xn0 = xnp[k0 + tig];
            float xn4 = xnp[k0 + tig + 4];
            unsigned bfr[2][2];
            #pragma unroll
            for (int nt = 0; nt < 2; nt++) {
                bfr[nt][0] = f2tf(W2s[(k0 + tig) * 132 + wn + nt * 8 + gid] * xn0);
                bfr[nt][1] = f2tf(W2s[(k0 + tig + 4) * 132 + wn + nt * 8 + gid] * xn4);
            }
            #pragma unroll
            for (int mt = 0; mt < 4; mt++) {
                unsigned a[4];
                a[0] = __float_as_uint(x2s[(mt * 16 + gid) * 132 + k0 + tig]);
                a[1] = __float_as_uint(x2s[(mt * 16 + gid + 8) * 132 + k0 + tig]);
                a[2] = __float_as_uint(x2s[(mt * 16 + gid) * 132 + k0 + tig + 4]);
                a[3] = __float_as_uint(x2s[(mt * 16 + gid + 8) * 132 + k0 + tig + 4]);
                mma_tf32(c[mt][0], a, bfr[0]);
                mma_tf32(c[mt][1], a, bfr[1]);
            }
        }
        float BnR[4];
        #pragma unroll
        for (int q = 0; q < 4; q++)
            BnR[q] = Bng[((size_t)b * NN + n) * HH + colv[q]];
        #pragma unroll
        for (int mt = 0; mt < 4; mt++) {
            float part0 = 0.0f, part1 = 0.0f;
            #pragma unroll
            for (int nt = 0; nt < 2; nt++)
                #pragma unroll
                for (int cc = 0; cc < 2; cc++) {
                    int q = nt * 2 + cc;
                    float v0 = c[mt][nt][cc]     + Areg[mt * 2][q]     + BnR[q];
                    float v1 = c[mt][nt][2 + cc] + Areg[mt * 2 + 1][q] + BnR[q];
                    part0 += fmaxf(v0, 0.0f) * w2r[q];
                    part1 += fmaxf(v1, 0.0f) * w2r[q];
                }
            part0 += __shfl_xor_sync(0xffffffffu, part0, 1);
            part0 += __shfl_xor_sync(0xffffffffu, part0, 2);
            part1 += __shfl_xor_sync(0xffffffffu, part1, 1);
            part1 += __shfl_xor_sync(0xffffffffu, part1, 2);
            if (tig == 0) {
                atomicAdd(&logits[(mt * 16 + gid) * 16 + n], part0);
                atomicAdd(&logits[(mt * 16 + gid + 8) * 16 + n], part1);
            }
        }
    }
    __syncthreads();
    if (tid < 64) {
        float m = -1e30f;
        #pragma unroll
        for (int n = 0; n < NN; n++) m = fmaxf(m, logits[tid * 16 + n]);
        float l = 0.0f;
        #pragma unroll
        for (int n = 0; n < NN; n++) {
            float p = fast_exp(logits[tid * 16 + n] - m);
            logits[tid * 16 + n] = p; l += p;
        }
        float inv = __fdividef(1.0f, l);
        #pragma unroll
        for (int n = 0; n < NN; n++) logits[tid * 16 + n] *= inv;
    }
    __syncthreads();
    for (int idx = tid; idx < 64 * HH; idx += 256) {
        int r = idx >> 7, cc = idx & 127;
        float o = x2[((size_t)b * SS + s0 + r) * HH + cc];
        #pragma unroll
        for (int n = 0; n < NN; n++) o += logits[r * 16 + n] * xns[n * HH + cc];
        out[((size_t)b * SS + s0 + r) * HH + cc] = o;
    }
}

// ---------------- launch ----------------
extern "C" void kernel_launch(void* const* d_in, const int* in_sizes, int n_in,
                              void* d_out, int out_size) {
    const float* x      = (const float*)d_in[0];
    const int*   mask   = (const int*)  d_in[1];
    const float* neighs = (const float*)d_in[2];
    const int*   nmask  = (const int*)  d_in[3];
    const float* wq = (const float*)d_in[4];  const float* bq = (const float*)d_in[5];
    const float* wk = (const float*)d_in[6];  const float* bk = (const float*)d_in[7];
    const float* wv = (const float*)d_in[8];  const float* bv = (const float*)d_in[9];
    const float* wo = (const float*)d_in[10]; const float* bo = (const float*)d_in[11];
    const float* ln1_g = (const float*)d_in[12]; const float* ln1_b = (const float*)d_in[13];
    const float* ln2_g = (const float*)d_in[14]; const float* ln2_b = (const float*)d_in[15];
    const float* ff_w1 = (const float*)d_in[16]; const float* ff_b1 = (const float*)d_in[17];
    const float* ff_w2 = (const float*)d_in[18]; const float* ff_b2 = (const float*)d_in[19];
    const float* au_w1 = (const float*)d_in[20]; const float* au_b1 = (const float*)d_in[21];
    const float* au_w2 = (const float*)d_in[22]; const float* au_b2 = (const float*)d_in[23];
    float* out = (float*)d_out;

    float *p_xn, *p_qkv, *p_attn, *p_x1, *p_h, *p_ffh, *p_x2, *p_A,
          *p_xnei, *p_Bn, *p_Wd, *p_Wnc, *p_Wqkv, *p_bqkv;
    cudaGetSymbolAddress((void**)&p_xn, g_xn);
    cudaGetSymbolAddress((void**)&p_qkv, g_qkv);
    cudaGetSymbolAddress((void**)&p_attn, g_attn);
    cudaGetSymbolAddress((void**)&p_x1, g_x1);
    cudaGetSymbolAddress((void**)&p_h, g_h);
    cudaGetSymbolAddress((void**)&p_ffh, g_ffh);
    cudaGetSymbolAddress((void**)&p_x2, g_x2);
    cudaGetSymbolAddress((void**)&p_A, g_A);
    cudaGetSymbolAddress((void**)&p_xnei, g_xnei);
    cudaGetSymbolAddress((void**)&p_Bn, g_Bn);
    cudaGetSymbolAddress((void**)&p_Wd, g_Wd);
    cudaGetSymbolAddress((void**)&p_Wnc, g_Wnc);
    cudaGetSymbolAddress((void**)&p_Wqkv, g_Wqkv);
    cudaGetSymbolAddress((void**)&p_bqkv, g_bqkv);

    const int neigh_shmem = (64 * 129 * 2 + 128 + 128 + 256) * 4;            // ~68 KB
    const int au_shmem = (64 * 132 + 128 * 132 + 2048 + 64 * 16) * 4;        // 113664 B
    const int ff2_shmem = (2 * TBM * 20 + 2 * TBK * 132 + TBM * 132) * 4;    // 104960 B
    cudaFuncSetAttribute(neigh_kernel, cudaFuncAttributeMaxDynamicSharedMemorySize, neigh_shmem);
    cudaFuncSetAttribute(au_kernel, cudaFuncAttributeMaxDynamicSharedMemorySize, au_shmem);
    cudaFuncSetAttribute(ff2_fused, cudaFuncAttributeMaxDynamicSharedMemorySize, ff2_shmem);

    // fork/join stream for the independent neighbor branch (capture-safe).
    cudaStream_t s2;
    cudaStreamCreateWithFlags(&s2, cudaStreamNonBlocking);
    cudaEvent_t eFork, eJoin;
    cudaEventCreateWithFlags(&eFork, cudaEventDisableTiming);
    cudaEventCreateWithFlags(&eJoin, cudaEventDisableTiming);

    prep_kernel<<<192, 256>>>(au_w1, wq, wk, wv, bq, bk, bv, p_Wd, p_Wnc, p_Wqkv, p_bqkv);
    cudaEventRecord(eFork, 0);
    cudaStreamWaitEvent(s2, eFork, 0);
    neigh_kernel<<<NN * BB, 256, neigh_shmem, s2>>>(neighs, nmask, wq, bq, wk, bk, wv, bv,
                                                    wo, bo, ln1_g, ln1_b, p_Wnc, p_xnei, p_Bn);
    cudaEventRecord(eJoin, s2);

    // main path
    ln_kernel<<<ROWS, 128>>>(x, ln1_g, ln1_b, p_xn);
    {
        dim3 g(384 / TBN, ROWS / TBM);
        sgemm_tc<<<g, 256>>>(p_xn, p_Wqkv, p_bqkv, nullptr, p_qkv, ROWS, HH, 384, 0);
    }
    attn_kernel<<<BB * NHEADS * 8, 128>>>(p_qkv, mask, p_attn);
    {
        dim3 g(1, ROWS / TBM);
        sgemm_tc<<<g, 256>>>(p_attn, wo, bo, x, p_x1, ROWS, HH, HH, 0);
    }
    ln_kernel<<<ROWS, 128>>>(p_x1, ln2_g, ln2_b, p_h);
    {
        dim3 g(FFD / TBN, ROWS / TBM);
        sgemm_tc<<<g, 256>>>(p_h, ff_w1, ff_b1, nullptr, p_ffh, ROWS, HH, FFD, 1);
    }
    {
        dim3 g(1, ROWS / TBM);
        ff2_fused<<<g, 256, ff2_shmem>>>(p_ffh, ff_w2, ff_b2, p_x1, p_x2,
                                         p_Wd, au_b1, p_A, FFD);
    }
    // join: au needs xnei/Bn from the neigh branch
    cudaStreamWaitEvent(0, eJoin, 0);
    {
        dim3 g(SS / 64, BB);
        au_kernel<<<g, 256, au_shmem>>>(p_x2, p_A, p_Bn, p_xnei, au_w1, au_w2, au_b2, out);
    }
}

// round 15
// speedup vs baseline: 1.2955x; 1.0134x over previous
#include <cuda_runtime.h>
#include <cuda_bf16.h>
#include <math.h>

// Problem dims
#define BB 32
#define SS 512
#define HH 128
#define NHEADS 4
#define DD 32
#define FFD 512
#define NN 16
#define SNN 64
#define ROWS (BB*SS)          // 16384

// ---------------- static device scratch ----------------
__device__ float g_xn  [ROWS*HH];
__device__ float g_qkv [ROWS*384];
__device__ float g_attn[ROWS*HH];
__device__ float g_x1  [ROWS*HH];
__device__ float g_h   [ROWS*HH];
__device__ float g_ffh [ROWS*FFD];
__device__ float g_x2  [ROWS*HH];
__device__ float g_A   [ROWS*HH];
__device__ float g_xnei[BB*NN*HH];
__device__ float g_Bn  [BB*NN*HH];
__device__ float g_Wd  [HH*HH];
__device__ float g_Wnc [HH*HH];
__device__ float g_Wqkv[HH*384];
__device__ float g_bqkv[384];

// ---------------- tf32 / mma / cp.async helpers ----------------------------
__device__ __forceinline__ unsigned f2tf(float f) {
    unsigned r;
    asm("cvt.rna.tf32.f32 %0, %1;" : "=r"(r) : "f"(f));
    return r;
}
__device__ __forceinline__ float f2tf_f(float f) { return __uint_as_float(f2tf(f)); }

__device__ __forceinline__ void mma_tf32(float* c, const unsigned* a, const unsigned* b) {
    asm volatile(
        "mma.sync.aligned.m16n8k8.row.col.f32.tf32.tf32.f32 "
        "{%0,%1,%2,%3}, {%4,%5,%6,%7}, {%8,%9}, {%0,%1,%2,%3};"
        : "+f"(c[0]), "+f"(c[1]), "+f"(c[2]), "+f"(c[3])
        : "r"(a[0]), "r"(a[1]), "r"(a[2]), "r"(a[3]), "r"(b[0]), "r"(b[1]));
}

__device__ __forceinline__ void cp16(void* smem, const void* gmem) {
    unsigned s = (unsigned)__cvta_generic_to_shared(smem);
    asm volatile("cp.async.cg.shared.global [%0], [%1], 16;\n" :: "r"(s), "l"(gmem));
}
#define CP_COMMIT() asm volatile("cp.async.commit_group;\n" ::: "memory")
#define CP_WAIT(n)  asm volatile("cp.async.wait_group %0;\n" :: "n"(n) : "memory")

// ---------------- fast exp: FMA-pipe polynomial (no MUFU) ----------------
__device__ __forceinline__ float fast_exp(float x) {
    float z = x * 1.4426950408889634f;
    z = fminf(fmaxf(z, -126.0f), 126.0f);
    float t = z + 12582912.0f;
    int n = __float_as_int(t) - 0x4B400000;
    float f = z - (t - 12582912.0f);
    float p = 0.0013333558f;
    p = fmaf(p, f, 0.0096181291f);
    p = fmaf(p, f, 0.0555041087f);
    p = fmaf(p, f, 0.2402265070f);
    p = fmaf(p, f, 0.6931471806f);
    p = fmaf(p, f, 1.0f);
    return __int_as_float(__float_as_int(p) + (n << 23));
}

__device__ __forceinline__ float gelu_fast(float x) {
    float u = 0.7978845608028654f * (x + 0.044715f * x * x * x);
    float t = fast_exp(-2.0f * u);
    return __fdividef(x, 1.0f + t);
}

// ---------------- prep ------------------------------------------------------
__global__ void prep_kernel(const float* __restrict__ au_w1,
                            const float* __restrict__ wq, const float* __restrict__ wk,
                            const float* __restrict__ wv,
                            const float* __restrict__ bq, const float* __restrict__ bk,
                            const float* __restrict__ bv,
                            float* __restrict__ Wd, float* __restrict__ Wnc,
                            float* __restrict__ Wqkv, float* __restrict__ bqkv) {
    int idx = blockIdx.x * blockDim.x + threadIdx.x;
    if (idx < HH * HH) {
        int h = idx >> 7, j = idx & 127;
        float w1 = au_w1[h * HH + j];
        float w3 = au_w1[(256 + h) * HH + j];
        float w4 = au_w1[(384 + h) * HH + j];
        Wd[idx]  = w1 - w3;
        Wnc[idx] = w3 + w4;
    }
    if (idx < HH * 384) {
        int h = idx / 384, c = idx % 384;
        float v = (c < 128) ? wq[h * 128 + c]
                 : (c < 256) ? wk[h * 128 + (c - 128)]
                             : wv[h * 128 + (c - 256)];
        Wqkv[idx] = v;
    }
    if (idx < 384) {
        bqkv[idx] = (idx < 128) ? bq[idx] : (idx < 256) ? bk[idx - 128] : bv[idx - 256];
    }
}

// ---------------- layernorm ------------------------------------------------
__global__ void ln_kernel(const float* __restrict__ x, const float* __restrict__ g,
                          const float* __restrict__ b, float* __restrict__ y) {
    int row = blockIdx.x;
    int t = threadIdx.x;
    float v = x[(size_t)row * HH + t];
    float s = v, s2 = v * v;
    #pragma unroll
    for (int o = 16; o > 0; o >>= 1) {
        s  += __shfl_xor_sync(0xffffffffu, s, o);
        s2 += __shfl_xor_sync(0xffffffffu, s2, o);
    }
    __shared__ float ws[8];
    if ((t & 31) == 0) { ws[t >> 5] = s; ws[4 + (t >> 5)] = s2; }
    __syncthreads();
    s  = ws[0] + ws[1] + ws[2] + ws[3];
    s2 = ws[4] + ws[5] + ws[6] + ws[7];
    float mean = s * (1.0f / HH);
    float var = s2 * (1.0f / HH) - mean * mean;
    float rs = rsqrtf(var + 1e-6f);
    y[(size_t)row * HH + t] = (v - mean) * rs * g[t] + b[t];
}

// ---------------- TF32 tensor-core GEMM: cp.async double-buffered ----------
#define TBM 128
#define TBN 128
#define TBK 16
__device__ __forceinline__ void gemm_issue_tile(
    const float* __restrict__ A, const float* __restrict__ W,
    float (*As)[20], float (*Ws)[132],
    int bm, int bn, int K, int N, int k0, int tid) {
    #pragma unroll
    for (int l = 0; l < 2; l++) {
        int ch = l * 256 + tid;
        int ar = ch >> 2, ac = ch & 3;          // 128 rows x 4 chunks
        cp16(&As[ar][ac * 4], &A[(size_t)(bm + ar) * K + k0 + ac * 4]);
        int wr = ch >> 5, wc = ch & 31;         // 16 rows x 32 chunks
        cp16(&Ws[wr][wc * 4], &W[(size_t)(k0 + wr) * N + bn + wc * 4]);
    }
}

__global__ __launch_bounds__(256) void sgemm_tc(
    const float* __restrict__ A, const float* __restrict__ W,
    const float* __restrict__ bias, const float* __restrict__ res,
    float* __restrict__ C, int M, int K, int N, int act) {
    __shared__ float As[2][TBM][20];
    __shared__ float Ws[2][TBK][132];
    int bm = blockIdx.y * TBM, bn = blockIdx.x * TBN;
    int tid = threadIdx.x;
    int wid = tid >> 5, lane = tid & 31;
    int gid = lane >> 2, tig = lane & 3;
    int wm = (wid >> 2) * 64, wn = (wid & 3) * 32;
    gemm_issue_tile(A, W, As[0], Ws[0], bm, bn, K, N, 0, tid);
    CP_COMMIT();
    float c[4][4][4] = {};
    int nk = K / TBK;
    for (int kt = 0; kt < nk; kt++) {
        int cur = kt & 1;
        if (kt + 1 < nk) {
            gemm_issue_tile(A, W, As[cur ^ 1], Ws[cur ^ 1], bm, bn, K, N, (kt + 1) * TBK, tid);
            CP_COMMIT();
            CP_WAIT(1);
        } else {
            CP_WAIT(0);
        }
        __syncthreads();
        #pragma unroll
        for (int ks = 0; ks < 2; ks++) {
            int k0 = ks * 8;
            unsigned a[4][4], b[4][2];
            #pragma unroll
            for (int mt = 0; mt < 4; mt++) {
                a[mt][0] = __float_as_uint(As[cur][wm + mt * 16 + gid    ][k0 + tig]);
                a[mt][1] = __float_as_uint(As[cur][wm + mt * 16 + gid + 8][k0 + tig]);
                a[mt][2] = __float_as_uint(As[cur][wm + mt * 16 + gid    ][k0 + tig + 4]);
                a[mt][3] = __float_as_uint(As[cur][wm + mt * 16 + gid + 8][k0 + tig + 4]);
            }
            #pragma unroll
            for (int nt = 0; nt < 4; nt++) {
                b[nt][0] = __float_as_uint(Ws[cur][k0 + tig    ][wn + nt * 8 + gid]);
                b[nt][1] = __float_as_uint(Ws[cur][k0 + tig + 4][wn + nt * 8 + gid]);
            }
            #pragma unroll
            for (int mt = 0; mt < 4; mt++)
                #pragma unroll
                for (int nt = 0; nt < 4; nt++)
                    mma_tf32(c[mt][nt], a[mt], b[nt]);
        }
        __syncthreads();
    }
    // epilogue
    #pragma unroll
    for (int mt = 0; mt < 4; mt++) {
        #pragma unroll
        for (int nt = 0; nt < 4; nt++) {
            int col = bn + wn + nt * 8 + tig * 2;
            float b0 = bias ? bias[col] : 0.0f;
            float b1 = bias ? bias[col + 1] : 0.0f;
            #pragma unroll
            for (int hh = 0; hh < 2; hh++) {
                int row = bm + wm + mt * 16 + gid + hh * 8;
                float v0 = c[mt][nt][hh * 2 + 0] + b0;
                float v1 = c[mt][nt][hh * 2 + 1] + b1;
                if (act == 1) { v0 = gelu_fast(v0); v1 = gelu_fast(v1); }
                if (res) {
                    const float2 rv = *(const float2*)&res[(size_t)row * N + col];
                    v0 += rv.x; v1 += rv.y;
                }
                float2 ov; ov.x = v0; ov.y = v1;
                *(float2*)&C[(size_t)row * N + col] = ov;
            }
        }
    }
}

// ---------------- WO-GEMM + LN2 fused: x1 = attn@wo + bo + x; h = LN(x1) ----
// N=128, K=128: each block owns 128 complete rows, so LN stats are in-block.
__global__ __launch_bounds__(256) void wo_ln_fused(
    const float* __restrict__ A, const float* __restrict__ W,
    const float* __restrict__ bias, const float* __restrict__ res,
    float* __restrict__ C,
    const float* __restrict__ g2, const float* __restrict__ b2,
    float* __restrict__ hout) {
    extern __shared__ float sh[];
    float* AsB  = sh;                       // 2*128*20 = 5120
    float* WsB  = AsB + 2 * TBM * 20;       // 2*16*132 = 4224
    float* x1sh = WsB + 2 * TBK * 132;      // 128*132  = 16896
    const int N = 128, K = 128;
    int bm = blockIdx.y * TBM;
    int tid = threadIdx.x;
    int wid = tid >> 5, lane = tid & 31;
    int gid = lane >> 2, tig = lane & 3;
    int wm = (wid >> 2) * 64, wn = (wid & 3) * 32;
    // pass 1: x1 = A@W + bias + res
    #pragma unroll
    for (int l = 0; l < 2; l++) {
        int ch = l * 256 + tid;
        int ar = ch >> 2, ac = ch & 3;
        cp16(&AsB[ar * 20 + ac * 4], &A[(size_t)(bm + ar) * K + ac * 4]);
        int wr = ch >> 5, wc = ch & 31;
        cp16(&WsB[wr * 132 + wc * 4], &W[(size_t)wr * N + wc * 4]);
    }
    CP_COMMIT();
    float c[4][4][4] = {};
    for (int kt = 0; kt < 8; kt++) {
        int cur = kt & 1;
        if (kt + 1 < 8) {
            int k0 = (kt + 1) * TBK;
            #pragma unroll
            for (int l = 0; l < 2; l++) {
                int ch = l * 256 + tid;
                int ar = ch >> 2, ac = ch & 3;
                cp16(&AsB[(cur ^ 1) * TBM * 20 + ar * 20 + ac * 4],
                     &A[(size_t)(bm + ar) * K + k0 + ac * 4]);
                int wr = ch >> 5, wc = ch & 31;
                cp16(&WsB[(cur ^ 1) * TBK * 132 + wr * 132 + wc * 4],
                     &W[(size_t)(k0 + wr) * N + wc * 4]);
            }
            CP_COMMIT();
            CP_WAIT(1);
        } else {
            CP_WAIT(0);
        }
        __syncthreads();
        const float* Asb = AsB + cur * TBM * 20;
        const float* Wsb = WsB + cur * TBK * 132;
        #pragma unroll
        for (int ks = 0; ks < 2; ks++) {
            int k0 = ks * 8;
            unsigned a[4][4], b[4][2];
            #pragma unroll
            for (int mt = 0; mt < 4; mt++) {
                a[mt][0] = __float_as_uint(Asb[(wm + mt * 16 + gid    ) * 20 + k0 + tig]);
                a[mt][1] = __float_as_uint(Asb[(wm + mt * 16 + gid + 8) * 20 + k0 + tig]);
                a[mt][2] = __float_as_uint(Asb[(wm + mt * 16 + gid    ) * 20 + k0 + tig + 4]);
                a[mt][3] = __float_as_uint(Asb[(wm + mt * 16 + gid + 8) * 20 + k0 + tig + 4]);
            }
            #pragma unroll
            for (int nt = 0; nt < 4; nt++) {
                b[nt][0] = __float_as_uint(Wsb[(k0 + tig    ) * 132 + wn + nt * 8 + gid]);
                b[nt][1] = __float_as_uint(Wsb[(k0 + tig + 4) * 132 + wn + nt * 8 + gid]);
            }
            #pragma unroll
            for (int mt = 0; mt < 4; mt++)
                #pragma unroll
                for (int nt = 0; nt < 4; nt++)
                    mma_tf32(c[mt][nt], a[mt], b[nt]);
        }
        __syncthreads();
    }
    // epilogue 1: x1 -> global + smem
    #pragma unroll
    for (int mt = 0; mt < 4; mt++) {
        #pragma unroll
        for (int nt = 0; nt < 4; nt++) {
            int col = wn + nt * 8 + tig * 2;
            float b0 = bias[col], b1_ = bias[col + 1];
            #pragma unroll
            for (int hh = 0; hh < 2; hh++) {
                int rloc = wm + mt * 16 + gid + hh * 8;
                int row = bm + rloc;
                float v0 = c[mt][nt][hh * 2 + 0] + b0;
                float v1 = c[mt][nt][hh * 2 + 1] + b1_;
                const float2 rv = *(const float2*)&res[(size_t)row * N + col];
                v0 += rv.x; v1 += rv.y;
                float2 ov; ov.x = v0; ov.y = v1;
                *(float2*)&C[(size_t)row * N + col] = ov;
                x1sh[rloc * 132 + col]     = v0;
                x1sh[rloc * 132 + col + 1] = v1;
            }
        }
    }
    __syncthreads();
    // pass 2: LN2 -> hout. Thread pair (t, t^1) splits each row's 128 cols.
    {
        int row = tid >> 1;
        int half = (tid & 1) * 64;
        const float* rp = x1sh + row * 132 + half;
        float s = 0.0f, s2 = 0.0f;
        #pragma unroll
        for (int cq = 0; cq < 16; cq++) {
            float4 v4 = *(const float4*)&rp[cq * 4];
            s  += (v4.x + v4.y) + (v4.z + v4.w);
            s2 += (v4.x * v4.x + v4.y * v4.y) + (v4.z * v4.z + v4.w * v4.w);
        }
        s  += __shfl_xor_sync(0xffffffffu, s, 1);
        s2 += __shfl_xor_sync(0xffffffffu, s2, 1);
        float mean = s * (1.0f / HH);
        float var = s2 * (1.0f / HH) - mean * mean;
        float rs = rsqrtf(var + 1e-6f);
        size_t gbase = (size_t)(bm + row) * HH + half;
        #pragma unroll
        for (int cq = 0; cq < 16; cq++) {
            float4 v4 = *(const float4*)&rp[cq * 4];
            const float4 gg = *(const float4*)&g2[half + cq * 4];
            const float4 bb = *(const float4*)&b2[half + cq * 4];
            float4 ov;
            ov.x = (v4.x - mean) * rs * gg.x + bb.x;
            ov.y = (v4.y - mean) * rs * gg.y + bb.y;
            ov.z = (v4.z - mean) * rs * gg.z + bb.z;
            ov.w = (v4.w - mean) * rs * gg.w + bb.w;
            *(float4*)&hout[gbase + cq * 4] = ov;
        }
    }
}

// ---------------- FF2 + A-GEMM fused: x2 = gelu_ffh@W2 + b2 + x1, A = x2@Wd + b1
__global__ __launch_bounds__(256) void ff2_fused(
    const float* __restrict__ A, const float* __restrict__ W,
    const float* __restrict__ bias, const float* __restrict__ res,
    float* __restrict__ C,
    const float* __restrict__ Wd, const float* __restrict__ b1v,
    float* __restrict__ Aout, int K) {
    extern __shared__ float sh[];
    float* AsB  = sh;                       // 2*128*20 = 5120
    float* WsB  = AsB + 2 * TBM * 20;       // 2*16*132 = 4224
    float* x2sh = WsB + 2 * TBK * 132;      // 128*132  = 16896
    const int N = 128;
    int bm = blockIdx.y * TBM;
    int tid = threadIdx.x;
    int wid = tid >> 5, lane = tid & 31;
    int gid = lane >> 2, tig = lane & 3;
    int wm = (wid >> 2) * 64, wn = (wid & 3) * 32;
    // ---- pass 1: x2 = act(A@W)+bias+res ----
    #pragma unroll
    for (int l = 0; l < 2; l++) {
        int ch = l * 256 + tid;
        int ar = ch >> 2, ac = ch & 3;
        cp16(&AsB[ar * 20 + ac * 4], &A[(size_t)(bm + ar) * K + ac * 4]);
        int wr = ch >> 5, wc = ch & 31;
        cp16(&WsB[wr * 132 + wc * 4], &W[(size_t)wr * N + wc * 4]);
    }
    CP_COMMIT();
    float c[4][4][4] = {};
    int nk = K / TBK;
    for (int kt = 0; kt < nk; kt++) {
        int cur = kt & 1;
        if (kt + 1 < nk) {
            int k0 = (kt + 1) * TBK;
            #pragma unroll
            for (int l = 0; l < 2; l++) {
                int ch = l * 256 + tid;
                int ar = ch >> 2, ac = ch & 3;
                cp16(&AsB[(cur ^ 1) * TBM * 20 + ar * 20 + ac * 4],
                     &A[(size_t)(bm + ar) * K + k0 + ac * 4]);
                int wr = ch >> 5, wc = ch & 31;
                cp16(&WsB[(cur ^ 1) * TBK * 132 + wr * 132 + wc * 4],
                     &W[(size_t)(k0 + wr) * N + wc * 4]);
            }
            CP_COMMIT();
            CP_WAIT(1);
        } else {
            CP_WAIT(0);
        }
        __syncthreads();
        const float* Asb = AsB + cur * TBM * 20;
        const float* Wsb = WsB + cur * TBK * 132;
        #pragma unroll
        for (int ks = 0; ks < 2; ks++) {
            int k0 = ks * 8;
            unsigned a[4][4], b[4][2];
            #pragma unroll
            for (int mt = 0; mt < 4; mt++) {
                a[mt][0] = __float_as_uint(Asb[(wm + mt * 16 + gid    ) * 20 + k0 + tig]);
                a[mt][1] = __float_as_uint(Asb[(wm + mt * 16 + gid + 8) * 20 + k0 + tig]);
                a[mt][2] = __float_as_uint(Asb[(wm + mt * 16 + gid    ) * 20 + k0 + tig + 4]);
                a[mt][3] = __float_as_uint(Asb[(wm + mt * 16 + gid + 8) * 20 + k0 + tig + 4]);
            }
            #pragma unroll
            for (int nt = 0; nt < 4; nt++) {
                b[nt][0] = __float_as_uint(Wsb[(k0 + tig    ) * 132 + wn + nt * 8 + gid]);
                b[nt][1] = __float_as_uint(Wsb[(k0 + tig + 4) * 132 + wn + nt * 8 + gid]);
            }
            #pragma unroll
            for (int mt = 0; mt < 4; mt++)
                #pragma unroll
                for (int nt = 0; nt < 4; nt++)
                    mma_tf32(c[mt][nt], a[mt], b[nt]);
        }
        __syncthreads();
    }
    // epilogue 1: write x2 to global + smem
    #pragma unroll
    for (int mt = 0; mt < 4; mt++) {
        #pragma unroll
        for (int nt = 0; nt < 4; nt++) {
            int col = wn + nt * 8 + tig * 2;
            float b0 = bias[col], b1_ = bias[col + 1];
            #pragma unroll
            for (int hh = 0; hh < 2; hh++) {
                int rloc = wm + mt * 16 + gid + hh * 8;
                int row = bm + rloc;
                float v0 = c[mt][nt][hh * 2 + 0] + b0;
                float v1 = c[mt][nt][hh * 2 + 1] + b1_;
                const float2 rv = *(const float2*)&res[(size_t)row * N + col];
                v0 += rv.x; v1 += rv.y;
                float2 ov; ov.x = v0; ov.y = v1;
                *(float2*)&C[(size_t)row * N + col] = ov;
                x2sh[rloc * 132 + col]     = v0;
                x2sh[rloc * 132 + col + 1] = v1;
            }
        }
    }
    // ---- pass 2: Aout = x2sh @ Wd + b1 (K=128) ----
    #pragma unroll
    for (int l = 0; l < 2; l++) {
        int ch = l * 256 + tid;
        int wr = ch >> 5, wc = ch & 31;
        cp16(&WsB[wr * 132 + wc * 4], &Wd[(size_t)wr * N + wc * 4]);
    }
    CP_COMMIT();
    __syncthreads();                       // x2sh visible to all
    float c2[4][4][4] = {};
    for (int kt = 0; kt < 8; kt++) {
        int cur = kt & 1;
        if (kt + 1 < 8) {
            int k0 = (kt + 1) * TBK;
            #pragma unroll
            for (int l = 0; l < 2; l++) {
                int ch = l * 256 + tid;
                int wr = ch >> 5, wc = ch & 31;
                cp16(&WsB[(cur ^ 1) * TBK * 132 + wr * 132 + wc * 4],
                     &Wd[(size_t)(k0 + wr) * N + wc * 4]);
            }
            CP_COMMIT();
            CP_WAIT(1);
        } else {
            CP_WAIT(0);
        }
        __syncthreads();
        const float* Wsb = WsB + cur * TBK * 132;
        int kb = kt * TBK;
        #pragma unroll
        for (int ks = 0; ks < 2; ks++) {
            int k0 = kb + ks * 8;
            unsigned a[4][4], b[4][2];
            #pragma unroll
            for (int mt = 0; mt < 4; mt++) {
                a[mt][0] = __float_as_uint(x2sh[(wm + mt * 16 + gid    ) * 132 + k0 + tig]);
                a[mt][1] = __float_as_uint(x2sh[(wm + mt * 16 + gid + 8) * 132 + k0 + tig]);
                a[mt][2] = __float_as_uint(x2sh[(wm + mt * 16 + gid    ) * 132 + k0 + tig + 4]);
                a[mt][3] = __float_as_uint(x2sh[(wm + mt * 16 + gid + 8) * 132 + k0 + tig + 4]);
            }
            #pragma unroll
            for (int nt = 0; nt < 4; nt++) {
                b[nt][0] = __float_as_uint(Wsb[(ks * 8 + tig    ) * 132 + wn + nt * 8 + gid]);
                b[nt][1] = __float_as_uint(Wsb[(ks * 8 + tig + 4) * 132 + wn + nt * 8 + gid]);
            }
            #pragma unroll
            for (int mt = 0; mt < 4; mt++)
                #pragma unroll
                for (int nt = 0; nt < 4; nt++)
                    mma_tf32(c2[mt][nt], a[mt], b[nt]);
        }
        __syncthreads();
    }
    // epilogue 2
    #pragma unroll
    for (int mt = 0; mt < 4; mt++) {
        #pragma unroll
        for (int nt = 0; nt < 4; nt++) {
            int col = wn + nt * 8 + tig * 2;
            float b0 = b1v[col], b1_ = b1v[col + 1];
            #pragma unroll
            for (int hh = 0; hh < 2; hh++) {
                int row = bm + wm + mt * 16 + gid + hh * 8;
                float2 ov;
                ov.x = c2[mt][nt][hh * 2 + 0] + b0;
                ov.y = c2[mt][nt][hh * 2 + 1] + b1_;
                *(float2*)&Aout[(size_t)row * N + col] = ov;
            }
        }
    }
}

// ---------------- flash attention: cp.async pipeline, Q in regs ------------
__global__ __launch_bounds__(128, 5) void attn_kernel(const float* __restrict__ qkv,
                                                      const int* __restrict__ mask,
                                                      float* __restrict__ o) {
    __shared__ float Ks[2][64][36];
    __shared__ float Vs[2][64][36];
    int blk = blockIdx.x;
    int qt = blk & 7, h = (blk >> 3) & 3, b = blk >> 5;
    int q0 = qt * 64;
    int tid = threadIdx.x;
    int w = tid >> 5, lane = tid & 31;
    int gid = lane >> 2, tig = lane & 3;
    const float* qbase = qkv + (size_t)(b * SS + q0) * 384 + h * 32;
    const float* kbase = qkv + (size_t)b * SS * 384 + 128 + h * 32;
    const float* vbase = qkv + (size_t)b * SS * 384 + 256 + h * 32;
    const float scale = 0.17677669529663687f;
    #pragma unroll
    for (int k = 0; k < 4; k++) {
        int idx = tid + k * 128;
        int r = idx >> 3, c4 = idx & 7;
        float4 v = *(const float4*)&qbase[(size_t)r * 384 + c4 * 4];
        v.x *= scale; v.y *= scale; v.z *= scale; v.w *= scale;
        *(float4*)&Ks[0][r][c4 * 4] = v;
    }
    __syncthreads();
    unsigned qa[4][4];
    #pragma unroll
    for (int ks = 0; ks < 4; ks++) {
        int k0 = ks * 8;
        qa[ks][0] = __float_as_uint(Ks[0][w * 16 + gid    ][k0 + tig]);
        qa[ks][1] = __float_as_uint(Ks[0][w * 16 + gid + 8][k0 + tig]);
        qa[ks][2] = __float_as_uint(Ks[0][w * 16 + gid    ][k0 + tig + 4]);
        qa[ks][3] = __float_as_uint(Ks[0][w * 16 + gid + 8][k0 + tig + 4]);
    }
    __syncthreads();
    #pragma unroll
    for (int k = 0; k < 4; k++) {
        int idx = tid + k * 128;
        int r = idx >> 3, c4 = idx & 7;
        cp16(&Ks[0][r][c4 * 4], &kbase[(size_t)r * 384 + c4 * 4]);
        cp16(&Vs[0][r][c4 * 4], &vbase[(size_t)r * 384 + c4 * 4]);
    }
    CP_COMMIT();
    float o_acc[4][4] = {};
    float m0 = -1e30f, l0 = 0.0f, m1 = -1e30f, l1 = 0.0f;
    const int* mbase = mask + (size_t)b * SS * SS + (size_t)q0 * SS;
    int src0 = (lane & ~3) + (tig >> 1);
    int src2 = src0 + 2;
    bool oddc = (tig & 1) != 0;
    for (int kt = 0; kt < 8; kt++) {
        int cur = kt & 1;
        if (kt + 1 < 8) {
            int cn = (kt + 1) * 64;
            #pragma unroll
            for (int k = 0; k < 4; k++) {
                int idx = tid + k * 128;
                int r = idx >> 3, c4 = idx & 7;
                cp16(&Ks[cur ^ 1][r][c4 * 4], &kbase[(size_t)(cn + r) * 384 + c4 * 4]);
                cp16(&Vs[cur ^ 1][r][c4 * 4], &vbase[(size_t)(cn + r) * 384 + c4 * 4]);
            }
            CP_COMMIT();
            CP_WAIT(1);
        } else {
            CP_WAIT(0);
        }
        __syncthreads();
        int c0k = kt * 64;
        float cs[8][4] = {};
        #pragma unroll
        for (int ks = 0; ks < 4; ks++) {
            int k0 = ks * 8;
            #pragma unroll
            for (int nt = 0; nt < 8; nt++) {
                unsigned bb[2];
                bb[0] = __float_as_uint(Ks[cur][nt * 8 + gid][k0 + tig]);
                bb[1] = __float_as_uint(Ks[cur][nt * 8 + gid][k0 + tig + 4]);
                mma_tf32(cs[nt], qa[ks], bb);
            }
        }
        const int2* mr0 = (const int2*)(mbase + (size_t)(w * 16 + gid) * SS + c0k);
        const int2* mr1 = (const int2*)(mbase + (size_t)(w * 16 + gid + 8) * SS + c0k);
        #pragma unroll
        for (int nt = 0; nt < 8; nt++) {
            int2 m0v = mr0[nt * 4 + tig];
            int2 m1v = mr1[nt * 4 + tig];
            if (m0v.x == 0) cs[nt][0] = -1e9f;
            if (m0v.y == 0) cs[nt][1] = -1e9f;
            if (m1v.x == 0) cs[nt][2] = -1e9f;
            if (m1v.y == 0) cs[nt][3] = -1e9f;
        }
        float t0 = cs[0][0], t1 = cs[0][2];
        #pragma unroll
        for (int nt = 0; nt < 8; nt++) {
            t0 = fmaxf(t0, fmaxf(cs[nt][0], cs[nt][1]));
            t1 = fmaxf(t1, fmaxf(cs[nt][2], cs[nt][3]));
        }
        t0 = fmaxf(t0, __shfl_xor_sync(0xffffffffu, t0, 1));
        t0 = fmaxf(t0, __shfl_xor_sync(0xffffffffu, t0, 2));
        t1 = fmaxf(t1, __shfl_xor_sync(0xffffffffu, t1, 1));
        t1 = fmaxf(t1, __shfl_xor_sync(0xffffffffu, t1, 2));
        float mn0 = fmaxf(m0, t0), mn1 = fmaxf(m1, t1);
        float corr0 = fast_exp(m0 - mn0), corr1 = fast_exp(m1 - mn1);
        float ps0 = 0.0f, ps1 = 0.0f;
        #pragma unroll
        for (int nt = 0; nt < 8; nt++) {
            cs[nt][0] = fast_exp(cs[nt][0] - mn0);
            cs[nt][1] = fast_exp(cs[nt][1] - mn0);
            cs[nt][2] = fast_exp(cs[nt][2] - mn1);
            cs[nt][3] = fast_exp(cs[nt][3] - mn1);
            ps0 += cs[nt][0] + cs[nt][1];
            ps1 += cs[nt][2] + cs[nt][3];
        }
        ps0 += __shfl_xor_sync(0xffffffffu, ps0, 1);
        ps0 += __shfl_xor_sync(0xffffffffu, ps0, 2);
        ps1 += __shfl_xor_sync(0xffffffffu, ps1, 1);
        ps1 += __shfl_xor_sync(0xffffffffu, ps1, 2);
        l0 = l0 * corr0 + ps0; m0 = mn0;
        l1 = l1 * corr1 + ps1; m1 = mn1;
        #pragma unroll
        for (int nt = 0; nt < 4; nt++) {
            o_acc[nt][0] *= corr0; o_acc[nt][1] *= corr0;
            o_acc[nt][2] *= corr1; o_acc[nt][3] *= corr1;
        }
        #pragma unroll
        for (int ks = 0; ks < 8; ks++) {
            float lo0 = __shfl_sync(0xffffffffu, cs[ks][0], src0);
            float hi0 = __shfl_sync(0xffffffffu, cs[ks][1], src0);
            float lo1 = __shfl_sync(0xffffffffu, cs[ks][2], src0);
            float hi1 = __shfl_sync(0xffffffffu, cs[ks][3], src0);
            float lo2 = __shfl_sync(0xffffffffu, cs[ks][0], src2);
            float hi2 = __shfl_sync(0xffffffffu, cs[ks][1], src2);
            float lo3 = __shfl_sync(0xffffffffu, cs[ks][2], src2);
            float hi3 = __shfl_sync(0xffffffffu, cs[ks][3], src2);
            unsigned a[4];
            a[0] = __float_as_uint(oddc ? hi0 : lo0);
            a[1] = __float_as_uint(oddc ? hi1 : lo1);
            a[2] = __float_as_uint(oddc ? hi2 : lo2);
            a[3] = __float_as_uint(oddc ? hi3 : lo3);
            int k0 = ks * 8;
            #pragma unroll
            for (int nt = 0; nt < 4; nt++) {
                unsigned bb[2];
                bb[0] = __float_as_uint(Vs[cur][k0 + tig    ][nt * 8 + gid]);
                bb[1] = __float_as_uint(Vs[cur][k0 + tig + 4][nt * 8 + gid]);
                mma_tf32(o_acc[nt], a, bb);
            }
        }
        __syncthreads();
    }
    float inv0 = __fdividef(1.0f, l0);
    float inv1 = __fdividef(1.0f, l1);
    #pragma unroll
    for (int nt = 0; nt < 4; nt++) {
        int col = h * 32 + nt * 8 + tig * 2;
        size_t row0 = (size_t)(b * SS + q0 + w * 16 + gid);
        float2 v0; v0.x = o_acc[nt][0] * inv0; v0.y = o_acc[nt][1] * inv0;
        *(float2*)&o[row0 * HH + col] = v0;
        float2 v1; v1.x = o_acc[nt][2] * inv1; v1.y = o_acc[nt][3] * inv1;
        *(float2*)&o[(row0 + 8) * HH + col] = v1;
    }
}

// ---------------- neighbor proj helper -------------------------------------
__device__ __forceinline__ void proj64(const float* ln, const float* __restrict__ W,
                                       const float* __restrict__ bias, float* out, int tid) {
    int c2 = (tid & 63) * 2;
    int q4 = tid >> 6;
    int r0 = q4 * 16;
    float acc0[16], acc1[16];
    float bv0 = bias[c2], bv1 = bias[c2 + 1];
    #pragma unroll
    for (int i = 0; i < 16; i++) { acc0[i] = bv0; acc1[i] = bv1; }
    #pragma unroll 4
    for (int hh = 0; hh < HH; hh++) {
        float2 w = *(const float2*)&W[hh * HH + c2];
        #pragma unroll
        for (int i = 0; i < 16; i++) {
            float a = ln[(r0 + i) * 129 + hh];
            acc0[i] += a * w.x;
            acc1[i] += a * w.y;
        }
    }
    #pragma unroll
    for (int i = 0; i < 16; i++) {
        out[(r0 + i) * 129 + c2] = acc0[i];
        out[(r0 + i) * 129 + c2 + 1] = acc1[i];
    }
}

// ---------------- neighbor attention (last-token only) + fused Bn ----------
__global__ void neigh_kernel(const float* __restrict__ neighs, const int* __restrict__ nmask,
                             const float* __restrict__ wq, const float* __restrict__ bq,
                             const float* __restrict__ wk, const float* __restrict__ bk,
                             const float* __restrict__ wv, const float* __restrict__ bv,
                             const float* __restrict__ wo, const float* __restrict__ bo,
                             const float* __restrict__ g1, const float* __restrict__ b1,
                             const float* __restrict__ Wnc,
                             float* __restrict__ xnei, float* __restrict__ Bn) {
    extern __shared__ float sh[];
    float* ln  = sh;
    float* kv  = ln + 64 * 129;
    float* qv  = kv + 64 * 129;
    float* osh = qv + 128;
    float* sc  = osh + 128;
    int tid = threadIdx.x;
    int nb = blockIdx.x;
    int n = nb / BB, b = nb % BB;
    const float* base = neighs + (size_t)nb * SNN * HH;
    for (int idx = tid; idx < SNN * HH; idx += 256) {
        int r = idx >> 7, c = idx & 127;
        ln[r * 129 + c] = base[idx];
    }
    __syncthreads();
    {
        int warp = tid >> 5, lane = tid & 31;
        for (int r = warp; r < SNN; r += 8) {
            float s = 0.0f, s2 = 0.0f;
            #pragma unroll
            for (int c = lane; c < HH; c += 32) {
                float v = ln[r * 129 + c];
                s += v; s2 += v * v;
            }
            #pragma unroll
            for (int o = 16; o > 0; o >>= 1) {
                s  += __shfl_xor_sync(0xffffffffu, s, o);
                s2 += __shfl_xor_sync(0xffffffffu, s2, o);
            }
            float mean = s * (1.0f / HH);
            float var = s2 * (1.0f / HH) - mean * mean;
            float rs = rsqrtf(var + 1e-6f);
            #pragma unroll
            for (int c = lane; c < HH; c += 32) {
                float v = ln[r * 129 + c];
                ln[r * 129 + c] = (v - mean) * rs * g1[c] + b1[c];
            }
        }
    }
    __syncthreads();
    proj64(ln, wk, bk, kv, tid);
    if (tid < HH) {
        float a = bq[tid];
        #pragma unroll 4
        for (int hh = 0; hh < HH; hh++) a += ln[63 * 129 + hh] * wq[hh * HH + tid];
        qv[tid] = a;
    }
    __syncthreads();
    {
        int head = tid >> 6, j = tid & 63;
        float s = 0.0f;
        #pragma unroll
        for (int d = 0; d < DD; d++) s += qv[head * DD + d] * kv[j * 129 + head * DD + d];
        s *= 0.17677669529663687f;
        int mval = nmask[((size_t)nb * SNN + (SNN - 1)) * SNN + j];
        if (mval == 0) s = -1e9f;
        sc[head * 64 + j] = s;
    }
    __syncthreads();
    if (tid < 4) {
        float m = -1e30f;
        for (int j = 0; j < 64; j++) m = fmaxf(m, sc[tid * 64 + j]);
        float l = 0.0f;
        for (int j = 0; j < 64; j++) {
            float p = fast_exp(sc[tid * 64 + j] - m);
            sc[tid * 64 + j] = p; l += p;
        }
        float inv = 1.0f / l;
        for (int j = 0; j < 64; j++) sc[tid * 64 + j] *= inv;
    }
    __syncthreads();
    proj64(ln, wv, bv, kv, tid);
    __syncthreads();
    if (tid < HH) {
        int head = tid >> 5;
        float o = 0.0f;
        #pragma unroll 4
        for (int j = 0; j < 64; j++) o += sc[head * 64 + j] * kv[j * 129 + tid];
        osh[tid] = o;
    }
    __syncthreads();
    if (tid < HH) {
        float r = bo[tid] + base[(SNN - 1) * HH + tid];
        #pragma unroll 4
        for (int hh = 0; hh < HH; hh++) r += osh[hh] * wo[hh * HH + tid];
        xnei[((size_t)b * NN + n) * HH + tid] = r;
        qv[tid] = r;                            // stash for Bn pass
    }
    __syncthreads();
    {
        int col = tid & 127;
        int kh = (tid >> 7) * 64;
        float acc = 0.0f;
        #pragma unroll 4
        for (int k = 0; k < 64; k++)
            acc += qv[kh + k] * Wnc[(size_t)(kh + k) * HH + col];
        sc[tid] = acc;
    }
    __syncthreads();
    if (tid < HH)
        Bn[((size_t)b * NN + n) * HH + tid] = sc[tid] + sc[tid + 128];
}

// ---------------- attention-pooling kernel (tf32 mma, B-scaled) ------------
__global__ __launch_bounds__(256) void au_kernel(
        const float* __restrict__ x2, const float* __restrict__ Ag,
        const float* __restrict__ Bng, const float* __restrict__ xnei,
        const float* __restrict__ au_w1, const float* __restrict__ au_w2,
        const float* __restrict__ au_b2, float* __restrict__ out) {
    extern __shared__ float sh[];
    float* x2s    = sh;                  // 64*132 tf32
    float* W2s    = x2s + 64 * 132;      // 128*132 tf32
    float* xns    = W2s + 128 * 132;     // 16*128 fp32
    float* logits = xns + 2048;          // 64*16
    int tid = threadIdx.x;
    int b = blockIdx.y;
    int s0 = blockIdx.x * 64;
    int w = tid >> 5, lane = tid & 31;
    int gid = lane >> 2, tig = lane & 3;
    int wn = w * 16;
    for (int idx = tid; idx < HH * HH; idx += 256) {
        int k = idx >> 7, nn = idx & 127;
        W2s[k * 132 + nn] = f2tf_f(au_w1[HH * HH + idx]);
    }
    for (int idx = tid; idx < 64 * HH; idx += 256) {
        int r = idx >> 7, cc = idx & 127;
        x2s[r * 132 + cc] = f2tf_f(x2[((size_t)b * SS + s0 + r) * HH + cc]);
    }
    for (int idx = tid; idx < NN * HH; idx += 256) xns[idx] = xnei[(size_t)b * NN * HH + idx];
    for (int idx = tid; idx < 64 * 16; idx += 256) logits[idx] = 0.0f;
    int colv[4];
    float w2r[4];
    #pragma unroll
    for (int q = 0; q < 4; q++) {
        colv[q] = wn + (q >> 1) * 8 + tig * 2 + (q & 1);
        w2r[q] = au_w2[colv[q]];
    }
    float Areg[8][4];
    #pragma unroll
    for (int mt = 0; mt < 4; mt++)
        #pragma unroll
        for (int hh = 0; hh < 2; hh++) {
            int r = mt * 16 + gid + hh * 8;
            #pragma unroll
            for (int q = 0; q < 4; q++)
                Areg[mt * 2 + hh][q] = Ag[((size_t)b * SS + s0 + r) * HH + colv[q]];
        }
    __syncthreads();
    for (int n = 0; n < NN; n++) {
        const float* xnp = xns + n * 128;
        float c[4][2][4] = {};
        #pragma unroll
        for (int ks = 0; ks < 16; ks++) {
            int k0 = ks * 8;
            float xn0 = xnp[k0 + tig];
            float xn4 = xnp[k0 + tig + 4];
            unsigned bfr[2][2];
            #pragma unroll
            for (int nt = 0; nt < 2; nt++) {
                bfr[nt][0] = f2tf(W2s[(k0 + tig) * 132 + wn + nt * 8 + gid] * xn0);
                bfr[nt][1] = f2tf(W2s[(k0 + tig + 4) * 132 + wn + nt * 8 + gid] * xn4);
            }
            #pragma unroll
            for (int mt = 0; mt < 4; mt++) {
                unsigned a[4];
                a[0] = __float_as_uint(x2s[(mt * 16 + gid) * 132 + k0 + tig]);
                a[1] = __float_as_uint(x2s[(mt * 16 + gid + 8) * 132 + k0 + tig]);
                a[2] = __float_as_uint(x2s[(mt * 16 + gid) * 132 + k0 + tig + 4]);
                a[3] = __float_as_uint(x2s[(mt * 16 + gid + 8) * 132 + k0 + tig + 4]);
                mma_tf32(c[mt][0], a, bfr[0]);
                mma_tf32(c[mt][1], a, bfr[1]);
            }
        }
        float BnR[4];
        #pragma unroll
        for (int q = 0; q < 4; q++)
            BnR[q] = Bng[((size_t)b * NN + n) * HH + colv[q]];
        #pragma unroll
        for (int mt = 0; mt < 4; mt++) {
            float part0 = 0.0f, part1 = 0.0f;
            #pragma unroll
            for (int nt = 0; nt < 2; nt++)
                #pragma unroll
                for (int cc = 0; cc < 2; cc++) {
                    int q = nt * 2 + cc;
                    float v0 = c[mt][nt][cc]     + Areg[mt * 2][q]     + BnR[q];
                    float v1 = c[mt][nt][2 + cc] + Areg[mt * 2 + 1][q] + BnR[q];
                    part0 += fmaxf(v0, 0.0f) * w2r[q];
                    part1 += fmaxf(v1, 0.0f) * w2r[q];
                }
            part0 += __shfl_xor_sync(0xffffffffu, part0, 1);
            part0 += __shfl_xor_sync(0xffffffffu, part0, 2);
            part1 += __shfl_xor_sync(0xffffffffu, part1, 1);
            part1 += __shfl_xor_sync(0xffffffffu, part1, 2);
            if (tig == 0) {
                atomicAdd(&logits[(mt * 16 + gid) * 16 + n], part0);
                atomicAdd(&logits[(mt * 16 + gid + 8) * 16 + n], part1);
            }
        }
    }
    __syncthreads();
    if (tid < 64) {
        float m = -1e30f;
        #pragma unroll
        for (int n = 0; n < NN; n++) m = fmaxf(m, logits[tid * 16 + n]);
        float l = 0.0f;
        #pragma unroll
        for (int n = 0; n < NN; n++) {
            float p = fast_exp(logits[tid * 16 + n] - m);
            logits[tid * 16 + n] = p; l += p;
        }
        float inv = __fdividef(1.0f, l);
        #pragma unroll
        for (int n = 0; n < NN; n++) logits[tid * 16 + n] *= inv;
    }
    __syncthreads();
    for (int idx = tid; idx < 64 * HH; idx += 256) {
        int r = idx >> 7, cc = idx & 127;
        float o = x2[((size_t)b * SS + s0 + r) * HH + cc];
        #pragma unroll
        for (int n = 0; n < NN; n++) o += logits[r * 16 + n] * xns[n * HH + cc];
        out[((size_t)b * SS + s0 + r) * HH + cc] = o;
    }
}

// ---------------- launch ----------------
extern "C" void kernel_launch(void* const* d_in, const int* in_sizes, int n_in,
                              void* d_out, int out_size) {
    const float* x      = (const float*)d_in[0];
    const int*   mask   = (const int*)  d_in[1];
    const float* neighs = (const float*)d_in[2];
    const int*   nmask  = (const int*)  d_in[3];
    const float* wq = (const float*)d_in[4];  const float* bq = (const float*)d_in[5];
    const float* wk = (const float*)d_in[6];  const float* bk = (const float*)d_in[7];
    const float* wv = (const float*)d_in[8];  const float* bv = (const float*)d_in[9];
    const float* wo = (const float*)d_in[10]; const float* bo = (const float*)d_in[11];
    const float* ln1_g = (const float*)d_in[12]; const float* ln1_b = (const float*)d_in[13];
    const float* ln2_g = (const float*)d_in[14]; const float* ln2_b = (const float*)d_in[15];
    const float* ff_w1 = (const float*)d_in[16]; const float* ff_b1 = (const float*)d_in[17];
    const float* ff_w2 = (const float*)d_in[18]; const float* ff_b2 = (const float*)d_in[19];
    const float* au_w1 = (const float*)d_in[20]; const float* au_b1 = (const float*)d_in[21];
    const float* au_w2 = (const float*)d_in[22]; const float* au_b2 = (const float*)d_in[23];
    float* out = (float*)d_out;

    float *p_xn, *p_qkv, *p_attn, *p_x1, *p_h, *p_ffh, *p_x2, *p_A,
          *p_xnei, *p_Bn, *p_Wd, *p_Wnc, *p_Wqkv, *p_bqkv;
    cudaGetSymbolAddress((void**)&p_xn, g_xn);
    cudaGetSymbolAddress((void**)&p_qkv, g_qkv);
    cudaGetSymbolAddress((void**)&p_attn, g_attn);
    cudaGetSymbolAddress((void**)&p_x1, g_x1);
    cudaGetSymbolAddress((void**)&p_h, g_h);
    cudaGetSymbolAddress((void**)&p_ffh, g_ffh);
    cudaGetSymbolAddress((void**)&p_x2, g_x2);
    cudaGetSymbolAddress((void**)&p_A, g_A);
    cudaGetSymbolAddress((void**)&p_xnei, g_xnei);
    cudaGetSymbolAddress((void**)&p_Bn, g_Bn);
    cudaGetSymbolAddress((void**)&p_Wd, g_Wd);
    cudaGetSymbolAddress((void**)&p_Wnc, g_Wnc);
    cudaGetSymbolAddress((void**)&p_Wqkv, g_Wqkv);
    cudaGetSymbolAddress((void**)&p_bqkv, g_bqkv);

    const int neigh_shmem = (64 * 129 * 2 + 128 + 128 + 256) * 4;            // ~68 KB
    const int au_shmem = (64 * 132 + 128 * 132 + 2048 + 64 * 16) * 4;        // 113664 B
    const int ff2_shmem = (2 * TBM * 20 + 2 * TBK * 132 + TBM * 132) * 4;    // 104960 B
    cudaFuncSetAttribute(neigh_kernel, cudaFuncAttributeMaxDynamicSharedMemorySize, neigh_shmem);
    cudaFuncSetAttribute(au_kernel, cudaFuncAttributeMaxDynamicSharedMemorySize, au_shmem);
    cudaFuncSetAttribute(ff2_fused, cudaFuncAttributeMaxDynamicSharedMemorySize, ff2_shmem);
    cudaFuncSetAttribute(wo_ln_fused, cudaFuncAttributeMaxDynamicSharedMemorySize, ff2_shmem);

    // fork/join stream for the independent neighbor branch (capture-safe).
    cudaStream_t s2;
    cudaStreamCreateWithFlags(&s2, cudaStreamNonBlocking);
    cudaEvent_t eFork, eJoin;
    cudaEventCreateWithFlags(&eFork, cudaEventDisableTiming);
    cudaEventCreateWithFlags(&eJoin, cudaEventDisableTiming);

    prep_kernel<<<192, 256>>>(au_w1, wq, wk, wv, bq, bk, bv, p_Wd, p_Wnc, p_Wqkv, p_bqkv);
    cudaEventRecord(eFork, 0);
    cudaStreamWaitEvent(s2, eFork, 0);
    neigh_kernel<<<NN * BB, 256, neigh_shmem, s2>>>(neighs, nmask, wq, bq, wk, bk, wv, bv,
                                                    wo, bo, ln1_g, ln1_b, p_Wnc, p_xnei, p_Bn);
    cudaEventRecord(eJoin, s2);

    // main path
    ln_kernel<<<ROWS, 128>>>(x, ln1_g, ln1_b, p_xn);
    {
        dim3 g(384 / TBN, ROWS / TBM);
        sgemm_tc<<<g, 256>>>(p_xn, p_Wqkv, p_bqkv, nullptr, p_qkv, ROWS, HH, 384, 0);
    }
    attn_kernel<<<BB * NHEADS * 8, 128>>>(p_qkv, mask, p_attn);
    {
        dim3 g(1, ROWS / TBM);
        wo_ln_fused<<<g, 256, ff2_shmem>>>(p_attn, wo, bo, x, p_x1, ln2_g, ln2_b, p_h);
    }
    {
        dim3 g(FFD / TBN, ROWS / TBM);
        sgemm_tc<<<g, 256>>>(p_h, ff_w1, ff_b1, nullptr, p_ffh, ROWS, HH, FFD, 1);
    }
    {
        dim3 g(1, ROWS / TBM);
        ff2_fused<<<g, 256, ff2_shmem>>>(p_ffh, ff_w2, ff_b2, p_x1, p_x2,
                                         p_Wd, au_b1, p_A, FFD);
    }
    // join: au needs xnei/Bn from the neigh branch
    cudaStreamWaitEvent(0, eJoin, 0);
    {
        dim3 g(SS / 64, BB);
        au_kernel<<<g, 256, au_shmem>>>(p_x2, p_A, p_Bn, p_xnei, au_w1, au_w2, au_b2, out);
    }
}